// round 1
// baseline (speedup 1.0000x reference)
#include <cuda_runtime.h>
#include <math.h>

// ---------------- problem constants ----------------
#define BSZ    32
#define SEQL   512
#define NVAR   32
#define PATCH  16
#define STRIDEP 8
#define DIM    512
#define NHEAD  8
#define NLAYER 4
#define HDIM   64
#define HIDDEN 1536
#define PNUM   64           // SEQL / STRIDEP
#define PRED   96
#define TOK    65536        // BSZ*PNUM*NVAR == BSZ*NVAR*PNUM
#define EPSR   1e-5f

// ---------------- device scratch (allocation-free) ----------------
__device__ float g_mean[BSZ * NVAR];
__device__ float g_std[BSZ * NVAR];
__device__ float g_cos[PNUM * (HDIM / 2)];
__device__ float g_sin[PNUM * (HDIM / 2)];

__device__ float g_hA[(size_t)TOK * DIM];      // residual stream (rel layout)
__device__ float g_hB[(size_t)TOK * DIM];      // residual stream (enc layout)
__device__ float g_hn[(size_t)TOK * DIM];      // normed activations
__device__ float g_q[(size_t)TOK * DIM];
__device__ float g_k[(size_t)TOK * DIM];
__device__ float g_v[(size_t)TOK * DIM];
__device__ float g_att[(size_t)TOK * DIM];
__device__ float g_f1[(size_t)TOK * HIDDEN];
__device__ float g_f3[(size_t)TOK * HIDDEN];
__device__ float g_z[BSZ * NVAR * PRED];

// buffer selector table (device-side so host never needs symbol addresses)
#define BUF_HA  0
#define BUF_HB  1
#define BUF_HN  2
#define BUF_Q   3
#define BUF_K   4
#define BUF_V   5
#define BUF_ATT 6
#define BUF_F1  7
#define BUF_F3  8
__device__ float* g_bufs[9] = {g_hA, g_hB, g_hn, g_q, g_k, g_v, g_att, g_f1, g_f3};

// ---------------- packed f32x2 helpers (sm_103a) ----------------
__device__ __forceinline__ unsigned long long pk2(float lo, float hi) {
    unsigned long long r;
    asm("mov.b64 %0, {%1,%2};" : "=l"(r) : "f"(lo), "f"(hi));
    return r;
}
__device__ __forceinline__ void fma2(unsigned long long& d, unsigned long long a, unsigned long long b) {
    asm("fma.rn.f32x2 %0, %1, %2, %0;" : "+l"(d) : "l"(a), "l"(b));
}
__device__ __forceinline__ void upk2(unsigned long long v, float& lo, float& hi) {
    asm("mov.b64 {%0,%1}, %2;" : "=f"(lo), "=f"(hi) : "l"(v));
}

// ---------------- per-(b,v) mean/std ----------------
__global__ void stats_kernel(const float* __restrict__ tokens) {
    int bv = blockIdx.x;          // b*NVAR + v
    int b = bv / NVAR, v = bv % NVAR;
    float s = 0.f, s2 = 0.f;
    for (int t = threadIdx.x; t < SEQL; t += blockDim.x) {
        float x = tokens[((size_t)b * SEQL + t) * NVAR + v];
        s += x; s2 += x * x;
    }
    __shared__ float sh0[128], sh1[128];
    sh0[threadIdx.x] = s; sh1[threadIdx.x] = s2;
    __syncthreads();
    for (int o = 64; o > 0; o >>= 1) {
        if (threadIdx.x < o) { sh0[threadIdx.x] += sh0[threadIdx.x + o]; sh1[threadIdx.x] += sh1[threadIdx.x + o]; }
        __syncthreads();
    }
    if (threadIdx.x == 0) {
        float m = sh0[0] / (float)SEQL;
        float var = sh1[0] / (float)SEQL - m * m;
        if (var < 0.f) var = 0.f;
        g_mean[bv] = m;
        g_std[bv] = sqrtf(var + EPSR);
    }
}

// ---------------- rope tables ----------------
__global__ void rope_init_kernel() {
    int i = threadIdx.x;   // 0..31
    int p = blockIdx.x;    // 0..63
    double inv = pow(10000.0, -((double)(2 * i)) / (double)HDIM);
    double ang = (double)p * inv;
    g_cos[p * (HDIM / 2) + i] = (float)cos(ang);
    g_sin[p * (HDIM / 2) + i] = (float)sin(ang);
}

// ---------------- patch embedding ----------------
// out token row (rel layout): t = (b*PNUM + p)*NVAR + v
__global__ void patch_embed_kernel(const float* __restrict__ tokens,
                                   const float* __restrict__ pe_w,
                                   const float* __restrict__ pe_b) {
    int bp = blockIdx.x;                 // b*PNUM + p
    int b = bp / PNUM, p = bp % PNUM;
    __shared__ float sp[NVAR * PATCH];   // [v][j], normalized patch values
    for (int i = threadIdx.x; i < NVAR * PATCH; i += blockDim.x) {
        int v = i / PATCH, j = i % PATCH;
        int sidx = p * STRIDEP + j;
        if (sidx > SEQL - 1) sidx = SEQL - 1;
        float x = tokens[((size_t)b * SEQL + sidx) * NVAR + v];
        int bv = b * NVAR + v;
        sp[i] = (x - g_mean[bv]) / g_std[bv];
    }
    __syncthreads();
    for (int o = threadIdx.x; o < NVAR * DIM; o += blockDim.x) {
        int v = o >> 9;            // /512
        int d = o & (DIM - 1);
        float acc = pe_b[d];
#pragma unroll
        for (int j = 0; j < PATCH; j++) acc += sp[v * PATCH + j] * pe_w[j * DIM + d];
        size_t t = (size_t)(b * PNUM + p) * NVAR + v;
        g_hA[t * DIM + d] = acc;
    }
}

// ---------------- rms norm (one block of 128 threads per 512-row) ----------------
__global__ void rmsnorm_kernel(int src_sel, int dst_sel, const float* __restrict__ w) {
    const float* src = g_bufs[src_sel];
    float* dst = g_bufs[dst_sel];
    size_t row = blockIdx.x;
    float4 xv = ((const float4*)(src + row * DIM))[threadIdx.x];
    float ss = xv.x * xv.x + xv.y * xv.y + xv.z * xv.z + xv.w * xv.w;
    for (int o = 16; o; o >>= 1) ss += __shfl_xor_sync(0xffffffffu, ss, o);
    __shared__ float sh[4];
    if ((threadIdx.x & 31) == 0) sh[threadIdx.x >> 5] = ss;
    __syncthreads();
    ss = sh[0] + sh[1] + sh[2] + sh[3];
    float r = rsqrtf(ss * (1.0f / DIM) + EPSR);
    float4 wv = ((const float4*)w)[threadIdx.x];
    float4 o4 = make_float4(xv.x * r * wv.x, xv.y * r * wv.y, xv.z * r * wv.z, xv.w * r * wv.w);
    ((float4*)(dst + row * DIM))[threadIdx.x] = o4;
}

// ---------------- stage transition: rmsnorm(norm_w) + layout remap rel->enc ----------------
__global__ void transition_kernel(const float* __restrict__ w) {
    size_t t = blockIdx.x;                         // rel row
    int v = (int)(t % NVAR);
    int bp = (int)(t / NVAR);
    int p = bp % PNUM, b = bp / PNUM;
    size_t t2 = (size_t)(b * NVAR + v) * PNUM + p; // enc row
    float4 xv = ((const float4*)(g_hA + t * DIM))[threadIdx.x];
    float ss = xv.x * xv.x + xv.y * xv.y + xv.z * xv.z + xv.w * xv.w;
    for (int o = 16; o; o >>= 1) ss += __shfl_xor_sync(0xffffffffu, ss, o);
    __shared__ float sh[4];
    if ((threadIdx.x & 31) == 0) sh[threadIdx.x >> 5] = ss;
    __syncthreads();
    ss = sh[0] + sh[1] + sh[2] + sh[3];
    float r = rsqrtf(ss * (1.0f / DIM) + EPSR);
    float4 wv = ((const float4*)w)[threadIdx.x];
    float4 o4 = make_float4(xv.x * r * wv.x, xv.y * r * wv.y, xv.z * r * wv.z, xv.w * r * wv.w);
    ((float4*)(g_hB + t2 * DIM))[threadIdx.x] = o4;
}

// ---------------- SGEMM: C[M,N] = A[M,K] @ B[K,N] (+residual), f32x2 inner ----------------
#define BM  128
#define BN  128
#define BKK 16
#define BMP 132   // padded to kill store bank conflicts, keeps 16B alignment

__global__ void __launch_bounds__(256) sgemm_kernel(int a_sel, const float* __restrict__ B,
                                                    int c_sel, int r_sel,
                                                    int M, int N, int K) {
    __shared__ __align__(16) float As[BKK][BMP];
    __shared__ __align__(16) float Bs[BKK][BN];
    const float* A = g_bufs[a_sel];
    float* C = g_bufs[c_sel];
    const float* Rz = (r_sel >= 0) ? g_bufs[r_sel] : (const float*)0;

    int bn = blockIdx.x * BN;
    int bm = blockIdx.y * BM;
    int tid = threadIdx.x;
    int tx = tid & 15;           // n-dir
    int ty = tid >> 4;           // m-dir
    int a_row = tid >> 2;        // 0..63
    int a_col = (tid & 3) << 2;  // 0,4,8,12
    int b_row = tid >> 5;        // 0..7
    int b_col = (tid & 31) << 2; // 0..124

    unsigned long long acc[8][4];
#pragma unroll
    for (int i = 0; i < 8; i++)
#pragma unroll
        for (int j = 0; j < 4; j++) acc[i][j] = 0ULL;

    const float* Ab = A + (size_t)bm * K;
    for (int k0 = 0; k0 < K; k0 += BKK) {
#pragma unroll
        for (int i = 0; i < 2; i++) {
            int m = a_row + i * 64;
            float4 va = *(const float4*)(Ab + (size_t)m * K + k0 + a_col);
            As[a_col + 0][m] = va.x;
            As[a_col + 1][m] = va.y;
            As[a_col + 2][m] = va.z;
            As[a_col + 3][m] = va.w;
        }
#pragma unroll
        for (int i = 0; i < 2; i++) {
            int kk = b_row + i * 8;
            int n = bn + b_col;
            float4 vb;
            if (n < N) vb = *(const float4*)(B + (size_t)(k0 + kk) * N + n);
            else vb = make_float4(0.f, 0.f, 0.f, 0.f);
            *(float4*)&Bs[kk][b_col] = vb;
        }
        __syncthreads();
#pragma unroll
        for (int kk = 0; kk < BKK; kk++) {
            float4 a0 = *(const float4*)&As[kk][ty * 8];
            float4 a1 = *(const float4*)&As[kk][ty * 8 + 4];
            ulonglong2 b0 = *(const ulonglong2*)&Bs[kk][tx * 8];
            ulonglong2 b1 = *(const ulonglong2*)&Bs[kk][tx * 8 + 4];
            unsigned long long bp[4] = {b0.x, b0.y, b1.x, b1.y};
            float av[8] = {a0.x, a0.y, a0.z, a0.w, a1.x, a1.y, a1.z, a1.w};
#pragma unroll
            for (int i = 0; i < 8; i++) {
                unsigned long long ap = pk2(av[i], av[i]);
#pragma unroll
                for (int j = 0; j < 4; j++) fma2(acc[i][j], ap, bp[j]);
            }
        }
        __syncthreads();
    }

#pragma unroll
    for (int i = 0; i < 8; i++) {
        int m = bm + ty * 8 + i;
        float* crow = C + (size_t)m * N;
        const float* rrow = Rz ? (Rz + (size_t)m * N) : (const float*)0;
#pragma unroll
        for (int j = 0; j < 4; j++) {
            int n = bn + tx * 8 + j * 2;
            float lo, hi;
            upk2(acc[i][j], lo, hi);
            if (n < N) {
                if (rrow) lo += rrow[n];
                crow[n] = lo;
            }
            if (n + 1 < N) {
                if (rrow) hi += rrow[n + 1];
                crow[n + 1] = hi;
            }
        }
    }
}

// ---------------- attention: one block per (head, batch-row), whole head in smem ----------------
__global__ void __launch_bounds__(256) attention_kernel(int S, int rope_mask) {
    __shared__ __align__(16) float s_a[PNUM * HDIM];   // q, later reused for v
    __shared__ __align__(16) float s_k[PNUM * HDIM];
    __shared__ float s_sc[PNUM * PNUM];
    int h = blockIdx.x;
    int bb = blockIdx.y;
    size_t base = (size_t)bb * S * DIM + h * HDIM;
    int tid = threadIdx.x;

    for (int i = tid; i < S * HDIM; i += 256) {
        int s = i / HDIM, d = i % HDIM;
        s_a[i] = g_q[base + (size_t)s * DIM + d];
        s_k[i] = g_k[base + (size_t)s * DIM + d];
    }
    __syncthreads();

    if (rope_mask) {
        for (int i = tid; i < S * (HDIM / 2); i += 256) {
            int s = i / (HDIM / 2), ii = i % (HDIM / 2);
            float c = g_cos[s * (HDIM / 2) + ii];
            float sn = g_sin[s * (HDIM / 2) + ii];
            float xr = s_a[s * HDIM + 2 * ii], xi = s_a[s * HDIM + 2 * ii + 1];
            s_a[s * HDIM + 2 * ii]     = xr * c - xi * sn;
            s_a[s * HDIM + 2 * ii + 1] = xr * sn + xi * c;
            xr = s_k[s * HDIM + 2 * ii]; xi = s_k[s * HDIM + 2 * ii + 1];
            s_k[s * HDIM + 2 * ii]     = xr * c - xi * sn;
            s_k[s * HDIM + 2 * ii + 1] = xr * sn + xi * c;
        }
        __syncthreads();
    }

    const float scale = 0.125f;   // 1/sqrt(64)
    for (int idx = tid; idx < S * S; idx += 256) {
        int i2 = idx / S, j = idx % S;
        if (rope_mask && j > i2) { s_sc[idx] = -INFINITY; continue; }
        const float4* qr = (const float4*)(s_a + i2 * HDIM);
        const float4* kr = (const float4*)(s_k + j * HDIM);
        float acc = 0.f;
#pragma unroll
        for (int d4 = 0; d4 < HDIM / 4; d4++) {
            float4 a = qr[d4], b = kr[d4];
            acc += a.x * b.x + a.y * b.y + a.z * b.z + a.w * b.w;
        }
        s_sc[idx] = acc * scale;
    }
    __syncthreads();

    // softmax: 256/S threads per row, contiguous lanes within a warp
    int tpr = 256 / S;
    int row = tid / tpr, g = tid % tpr;
    float m = -INFINITY;
    for (int j = g; j < S; j += tpr) m = fmaxf(m, s_sc[row * S + j]);
    for (int off = tpr >> 1; off; off >>= 1) m = fmaxf(m, __shfl_xor_sync(0xffffffffu, m, off));
    float sum = 0.f;
    for (int j = g; j < S; j += tpr) {
        float e = __expf(s_sc[row * S + j] - m);
        s_sc[row * S + j] = e;
        sum += e;
    }
    for (int off = tpr >> 1; off; off >>= 1) sum += __shfl_xor_sync(0xffffffffu, sum, off);
    float inv = 1.0f / sum;
    for (int j = g; j < S; j += tpr) s_sc[row * S + j] *= inv;
    __syncthreads();

    // reuse s_a as V
    for (int i = tid; i < S * HDIM; i += 256) {
        int s = i / HDIM, d = i % HDIM;
        s_a[i] = g_v[base + (size_t)s * DIM + d];
    }
    __syncthreads();

    for (int idx = tid; idx < S * HDIM; idx += 256) {
        int i2 = idx / HDIM, d = idx % HDIM;
        float acc = 0.f;
        for (int j = 0; j < S; j++) acc += s_sc[i2 * S + j] * s_a[j * HDIM + d];
        g_att[base + (size_t)i2 * DIM + d] = acc;
    }
}

// ---------------- fused silu(f1)*f3 -> f1 ----------------
__global__ void silu_mul_kernel() {
    size_t i = ((size_t)blockIdx.x * blockDim.x + threadIdx.x) * 4;
    float4 a = *(float4*)(g_f1 + i);
    float4 b = *(const float4*)(g_f3 + i);
    a.x = a.x / (1.f + __expf(-a.x)) * b.x;
    a.y = a.y / (1.f + __expf(-a.y)) * b.y;
    a.z = a.z / (1.f + __expf(-a.z)) * b.z;
    a.w = a.w / (1.f + __expf(-a.w)) * b.w;
    *(float4*)(g_f1 + i) = a;
}

// ---------------- head GEMM: z[1024,96] = hn_flat[1024,32768] @ head_w + head_b ----------------
__global__ void __launch_bounds__(256) head_kernel(const float* __restrict__ Bw,
                                                   const float* __restrict__ bias) {
    int r = blockIdx.x;          // 0..BSZ*NVAR-1
    int n0 = blockIdx.y * 8;     // 0..88
    const float* arow = g_hn + (size_t)r * (PNUM * DIM);
    float acc[8] = {0.f, 0.f, 0.f, 0.f, 0.f, 0.f, 0.f, 0.f};
    for (int kidx = threadIdx.x; kidx < PNUM * DIM; kidx += 256) {
        float a = arow[kidx];
        const float* br = Bw + (size_t)kidx * PRED + n0;
#pragma unroll
        for (int j = 0; j < 8; j++) acc[j] += a * br[j];
    }
    __shared__ float sh[8][8];
    int lane = threadIdx.x & 31, wid = threadIdx.x >> 5;
#pragma unroll
    for (int j = 0; j < 8; j++) {
        float v = acc[j];
        for (int off = 16; off; off >>= 1) v += __shfl_xor_sync(0xffffffffu, v, off);
        if (lane == 0) sh[wid][j] = v;
    }
    __syncthreads();
    if (threadIdx.x < 8) {
        float s2 = 0.f;
#pragma unroll
        for (int w = 0; w < 8; w++) s2 += sh[w][threadIdx.x];
        g_z[(size_t)r * PRED + n0 + threadIdx.x] = s2 + bias[n0 + threadIdx.x];
    }
}

// ---------------- final de-normalization + transpose ----------------
__global__ void finalize_kernel(float* __restrict__ out) {
    int i = blockIdx.x * blockDim.x + threadIdx.x;   // (b*PRED + t)*NVAR + v
    if (i >= BSZ * PRED * NVAR) return;
    int v = i % NVAR;
    int bt = i / NVAR;
    int t = bt % PRED;
    int b = bt / PRED;
    int bv = b * NVAR + v;
    out[i] = g_z[(size_t)bv * PRED + t] * g_std[bv] + g_mean[bv];
}

// ---------------- driver ----------------
extern "C" void kernel_launch(void* const* d_in, const int* in_sizes, int n_in,
                              void* d_out, int out_size) {
    const float* in[24];
    for (int i = 0; i < 24 && i < n_in; i++) in[i] = (const float*)d_in[i];

    const float *tokens = in[0], *pe_w = in[1], *pe_b = in[2];
    const float *norm_w, *head_w, *head_b;
    const float* W[2][9]; // [stage][wq,wk,wv,wo,w1,w2,w3,an,fn]

    if (in_sizes[3] == 512) {
        // dict insertion order: tokens, pe_w, pe_b, norm_w, head_w, head_b, rel..., enc...
        norm_w = in[3]; head_w = in[4]; head_b = in[5];
        for (int s = 0; s < 2; s++)
            for (int j = 0; j < 9; j++) W[s][j] = in[6 + s * 9 + j];
    } else {
        // signature order: tokens, pe_w, pe_b, rel..., enc..., norm_w, head_w, head_b
        for (int s = 0; s < 2; s++)
            for (int j = 0; j < 9; j++) W[s][j] = in[3 + s * 9 + j];
        norm_w = in[21]; head_w = in[22]; head_b = in[23];
    }

    stats_kernel<<<BSZ * NVAR, 128>>>(tokens);
    rope_init_kernel<<<PNUM, HDIM / 2>>>();
    patch_embed_kernel<<<BSZ * PNUM, 256>>>(tokens, pe_w, pe_b);

    dim3 gD(DIM / BN, TOK / BM);        // (4, 512)
    dim3 gH(HIDDEN / BN, TOK / BM);     // (12, 512)

    for (int stage = 0; stage < 2; stage++) {
        int S = stage ? PNUM : NVAR;
        int nb = TOK / S;
        int stream_sel = stage ? BUF_HB : BUF_HA;
        for (int i = 0; i < NLAYER; i++) {
            const float* wq = W[stage][0] + (size_t)i * DIM * DIM;
            const float* wk = W[stage][1] + (size_t)i * DIM * DIM;
            const float* wv = W[stage][2] + (size_t)i * DIM * DIM;
            const float* wo = W[stage][3] + (size_t)i * DIM * DIM;
            const float* w1 = W[stage][4] + (size_t)i * DIM * HIDDEN;
            const float* w2 = W[stage][5] + (size_t)i * HIDDEN * DIM;
            const float* w3 = W[stage][6] + (size_t)i * DIM * HIDDEN;
            const float* an = W[stage][7] + (size_t)i * DIM;
            const float* fn = W[stage][8] + (size_t)i * DIM;

            rmsnorm_kernel<<<TOK, 128>>>(stream_sel, BUF_HN, an);
            sgemm_kernel<<<gD, 256>>>(BUF_HN, wq, BUF_Q, -1, TOK, DIM, DIM);
            sgemm_kernel<<<gD, 256>>>(BUF_HN, wk, BUF_K, -1, TOK, DIM, DIM);
            sgemm_kernel<<<gD, 256>>>(BUF_HN, wv, BUF_V, -1, TOK, DIM, DIM);
            attention_kernel<<<dim3(NHEAD, nb), 256>>>(S, stage);
            sgemm_kernel<<<gD, 256>>>(BUF_ATT, wo, stream_sel, stream_sel, TOK, DIM, DIM);
            rmsnorm_kernel<<<TOK, 128>>>(stream_sel, BUF_HN, fn);
            sgemm_kernel<<<gH, 256>>>(BUF_HN, w1, BUF_F1, -1, TOK, HIDDEN, DIM);
            sgemm_kernel<<<gH, 256>>>(BUF_HN, w3, BUF_F3, -1, TOK, HIDDEN, DIM);
            silu_mul_kernel<<<(TOK * (size_t)HIDDEN) / 1024, 256>>>();
            sgemm_kernel<<<gD, 256>>>(BUF_F1, w2, stream_sel, stream_sel, TOK, DIM, HIDDEN);
        }
        if (stage == 0) {
            transition_kernel<<<TOK, 128>>>(norm_w);
        }
    }

    rmsnorm_kernel<<<TOK, 128>>>(BUF_HB, BUF_HN, norm_w);
    head_kernel<<<dim3(BSZ * NVAR, PRED / 8), 256>>>(head_w, head_b);
    finalize_kernel<<<(BSZ * PRED * NVAR) / 256, 256>>>((float*)d_out);
    (void)out_size; (void)n_in;
}

// round 4
// speedup vs baseline: 2.5637x; 2.5637x over previous
#include <cuda_runtime.h>
#include <cuda_bf16.h>
#include <math.h>
#include <stdint.h>

// ---------------- problem constants ----------------
#define BSZ    32
#define SEQL   512
#define NVAR   32
#define PATCH  16
#define STRIDEP 8
#define DIM    512
#define NHEAD  8
#define NLAYER 4
#define HDIM   64
#define HIDDEN 1536
#define PNUM   64
#define PRED   96
#define TOK    65536
#define EPSR   1e-5f

#if defined(__CUDA_ARCH_FEAT_SM103_ALL) || defined(__CUDA_ARCH_FEAT_SM100_ALL)
#define HAS_TCGEN05 1
#else
#define HAS_TCGEN05 0
#endif

// ---------------- helpers ----------------
#define SMEM_SWIZZLE_128B(o) ((uint32_t)(o) ^ ((((uint32_t)(o)) >> 3) & 0x70))

// SW128 smem descriptor base as a pure macro (no __device__ storage — it must
// exist identically in every arch pass or the cudafe registration stub breaks).
#define SMEM_DESC_BASE_SW128_C ((2ULL << 61) | (1ULL << 46) | (64ULL << 32) | (1ULL << 16))
#define MAKE_SMEM_DESC(a) (SMEM_DESC_BASE_SW128_C | ((unsigned long long)(((a) >> 4) & 0x3FFF)))

static __device__ __forceinline__ uint32_t smem_u32(const void* p) {
    uint32_t a;
    asm("{ .reg .u64 t; cvta.to.shared.u64 t, %1; cvt.u32.u64 %0, t; }" : "=r"(a) : "l"(p));
    return a;
}

__device__ __forceinline__ void cp16(uint32_t dst, const void* src) {
    asm volatile("cp.async.cg.shared.global [%0], [%1], 16;" :: "r"(dst), "l"(src) : "memory");
}
__device__ __forceinline__ void cp_commit() { asm volatile("cp.async.commit_group;" ::: "memory"); }

#if HAS_TCGEN05
#define TCGEN05_ALLOC(smem_result_addr, nCols) \
    asm volatile("tcgen05.alloc.cta_group::1.sync.aligned.shared::cta.b32 [%0], %1;" \
        :: "r"((uint32_t)(smem_result_addr)), "r"((uint32_t)(nCols)) : "memory")
#define TCGEN05_DEALLOC(tmem_addr, nCols) \
    asm volatile("tcgen05.dealloc.cta_group::1.sync.aligned.b32 %0, %1;" \
        :: "r"(tmem_addr), "r"((uint32_t)(nCols)))
#define TCGEN05_COMMIT(mbar_smem_addr) \
    asm volatile("tcgen05.commit.cta_group::1.mbarrier::arrive::one.shared::cluster.b64 [%0];" \
        :: "r"((uint32_t)(mbar_smem_addr)) : "memory")
#define TCGEN05_WAIT_LD() asm volatile("tcgen05.wait::ld.sync.aligned;" ::: "memory")
#define TCGEN05_FENCE_BEFORE() asm volatile("tcgen05.fence::before_thread_sync;" ::: "memory")
#define TCGEN05_FENCE_AFTER()  asm volatile("tcgen05.fence::after_thread_sync;" ::: "memory")

#define MBARRIER_INIT(mbar_smem_addr, count) \
    asm volatile("mbarrier.init.shared.b64 [%0], %1;" \
        :: "r"((uint32_t)(mbar_smem_addr)), "r"((uint32_t)(count)) : "memory")

#define MBARRIER_WAIT_PARITY(mbar_smem_addr, phase_parity) do { \
    uint32_t _mbar = (uint32_t)(mbar_smem_addr); \
    uint32_t _parity = (uint32_t)(phase_parity); \
    uint32_t _done; \
    asm volatile( \
        "{\n\t" \
        ".reg .pred p;\n\t" \
        "mbarrier.try_wait.parity.acquire.cta.shared::cta.b64 p, [%1], %2;\n\t" \
        "selp.b32 %0, 1, 0, p;\n\t" \
        "}" \
        : "=r"(_done) : "r"(_mbar), "r"(_parity) : "memory"); \
    if (!_done) { \
        asm volatile( \
            "{\n\t" \
            ".reg .pred P1;\n\t" \
            "WAIT_LOOP_%=:\n\t" \
            "mbarrier.try_wait.parity.acquire.cta.shared::cta.b64 P1, [%0], %1, 0x989680;\n\t" \
            "@P1 bra.uni WAIT_DONE_%=;\n\t" \
            "bra.uni WAIT_LOOP_%=;\n\t" \
            "WAIT_DONE_%=:\n\t" \
            "}" \
            :: "r"(_mbar), "r"(_parity) : "memory"); \
    } \
} while(0)

#define TCGEN05_LD_32X32B_X32(r, tmem_addr) \
    asm volatile( \
        "tcgen05.ld.sync.aligned.32x32b.x32.b32 " \
        "{%0, %1, %2, %3, %4, %5, %6, %7, " \
        " %8, %9, %10, %11, %12, %13, %14, %15, " \
        " %16, %17, %18, %19, %20, %21, %22, %23, " \
        " %24, %25, %26, %27, %28, %29, %30, %31}, [%32];" \
        : "=r"((r)[0]),  "=r"((r)[1]),  "=r"((r)[2]),  "=r"((r)[3]), \
          "=r"((r)[4]),  "=r"((r)[5]),  "=r"((r)[6]),  "=r"((r)[7]), \
          "=r"((r)[8]),  "=r"((r)[9]),  "=r"((r)[10]), "=r"((r)[11]), \
          "=r"((r)[12]), "=r"((r)[13]), "=r"((r)[14]), "=r"((r)[15]), \
          "=r"((r)[16]), "=r"((r)[17]), "=r"((r)[18]), "=r"((r)[19]), \
          "=r"((r)[20]), "=r"((r)[21]), "=r"((r)[22]), "=r"((r)[23]), \
          "=r"((r)[24]), "=r"((r)[25]), "=r"((r)[26]), "=r"((r)[27]), \
          "=r"((r)[28]), "=r"((r)[29]), "=r"((r)[30]), "=r"((r)[31]) \
        : "r"(tmem_addr))

__device__ __forceinline__ void mma_bf16_ss(uint32_t d, unsigned long long ad,
                                            unsigned long long bd, uint32_t idesc, bool acc) {
    uint32_t e = acc ? 1u : 0u;
    asm volatile(
        "{\n\t"
        ".reg .pred p;\n\t"
        "setp.ne.u32 p, %5, 0;\n\t"
        "tcgen05.mma.cta_group::1.kind::f16 [%0], %1, %2, %3, {%4, %4, %4, %4}, p;\n\t"
        "}"
        :: "r"(d), "l"(ad), "l"(bd), "r"(idesc), "r"(0u), "r"(e)
        : "memory");
}
#else
// ---- fallback: ampere-style mma.sync bf16 (plain sm_103 target) ----
__device__ __forceinline__ void ldmx4(uint32_t* r, uint32_t addr) {
    asm volatile("ldmatrix.sync.aligned.m8n8.x4.shared.b16 {%0,%1,%2,%3}, [%4];"
        : "=r"(r[0]), "=r"(r[1]), "=r"(r[2]), "=r"(r[3]) : "r"(addr));
}
__device__ __forceinline__ void mma16816(float* c, const uint32_t* a, const uint32_t* b) {
    asm volatile("mma.sync.aligned.m16n8k16.row.col.f32.bf16.bf16.f32 "
        "{%0,%1,%2,%3},{%4,%5,%6,%7},{%8,%9},{%0,%1,%2,%3};"
        : "+f"(c[0]), "+f"(c[1]), "+f"(c[2]), "+f"(c[3])
        : "r"(a[0]), "r"(a[1]), "r"(a[2]), "r"(a[3]), "r"(b[0]), "r"(b[1]));
}
#endif

// ---------------- device scratch ----------------
__device__ float g_mean[BSZ * NVAR];
__device__ float g_std[BSZ * NVAR];
__device__ float g_cos[PNUM * (HDIM / 2)];
__device__ float g_sin[PNUM * (HDIM / 2)];

__device__ __align__(256) float g_hA[(size_t)TOK * DIM];
__device__ __align__(256) float g_hB[(size_t)TOK * DIM];
__device__ __align__(256) float g_hn[(size_t)TOK * DIM];
__device__ __align__(256) float g_q[(size_t)TOK * DIM];
__device__ __align__(256) float g_k[(size_t)TOK * DIM];
__device__ __align__(256) float g_v[(size_t)TOK * DIM];
__device__ __align__(256) float g_f1[(size_t)TOK * HIDDEN];
__device__ __align__(256) float g_f3[(size_t)TOK * HIDDEN];
__device__ float g_z[BSZ * NVAR * PRED];

#define BUF_HA  0
#define BUF_HB  1
#define BUF_HN  2
#define BUF_Q   3
#define BUF_K   4
#define BUF_V   5
#define BUF_F1  6
#define BUF_F3  7
__device__ float* g_bufs[8] = {g_hA, g_hB, g_hn, g_q, g_k, g_v, g_f1, g_f3};

// bf16 hi/lo activation pairs: 0=hn [TOK,DIM], 1=att [TOK,DIM], 2=f1s [TOK,HIDDEN]
__device__ __align__(256) __nv_bfloat16 g_hn16H[(size_t)TOK * DIM];
__device__ __align__(256) __nv_bfloat16 g_hn16L[(size_t)TOK * DIM];
__device__ __align__(256) __nv_bfloat16 g_att16H[(size_t)TOK * DIM];
__device__ __align__(256) __nv_bfloat16 g_att16L[(size_t)TOK * DIM];
__device__ __align__(256) __nv_bfloat16 g_f116H[(size_t)TOK * HIDDEN];
__device__ __align__(256) __nv_bfloat16 g_f116L[(size_t)TOK * HIDDEN];
__device__ __nv_bfloat16* g_bufs16[6] = {g_hn16H, g_hn16L, g_att16H, g_att16L, g_f116H, g_f116L};

// transposed weights [N,K] bf16 hi/lo
#define WT_LAYER 3407872
#define WT_TOTAL ((size_t)WT_LAYER * 8)
__device__ __align__(256) __nv_bfloat16 g_wtH[WT_TOTAL];
__device__ __align__(256) __nv_bfloat16 g_wtL[WT_TOTAL];
#define OFF_Q  0
#define OFF_K  262144
#define OFF_V  524288
#define OFF_O  786432
#define OFF_W1 1048576
#define OFF_W3 1835008
#define OFF_W2 2621440

// ---------------- stats ----------------
__global__ void stats_kernel(const float* __restrict__ tokens) {
    int bv = blockIdx.x;
    int b = bv / NVAR, v = bv % NVAR;
    float s = 0.f, s2 = 0.f;
    for (int t = threadIdx.x; t < SEQL; t += blockDim.x) {
        float x = tokens[((size_t)b * SEQL + t) * NVAR + v];
        s += x; s2 += x * x;
    }
    __shared__ float sh0[128], sh1[128];
    sh0[threadIdx.x] = s; sh1[threadIdx.x] = s2;
    __syncthreads();
    for (int o = 64; o > 0; o >>= 1) {
        if (threadIdx.x < o) { sh0[threadIdx.x] += sh0[threadIdx.x + o]; sh1[threadIdx.x] += sh1[threadIdx.x + o]; }
        __syncthreads();
    }
    if (threadIdx.x == 0) {
        float m = sh0[0] / (float)SEQL;
        float var = sh1[0] / (float)SEQL - m * m;
        if (var < 0.f) var = 0.f;
        g_mean[bv] = m;
        g_std[bv] = sqrtf(var + EPSR);
    }
}

__global__ void rope_init_kernel() {
    int i = threadIdx.x;
    int p = blockIdx.x;
    double inv = pow(10000.0, -((double)(2 * i)) / (double)HDIM);
    double ang = (double)p * inv;
    g_cos[p * (HDIM / 2) + i] = (float)cos(ang);
    g_sin[p * (HDIM / 2) + i] = (float)sin(ang);
}

// ---------------- patch embedding ----------------
__global__ void patch_embed_kernel(const float* __restrict__ tokens,
                                   const float* __restrict__ pe_w,
                                   const float* __restrict__ pe_b) {
    int bp = blockIdx.x;
    int b = bp / PNUM, p = bp % PNUM;
    __shared__ float sp[NVAR * PATCH];
    for (int i = threadIdx.x; i < NVAR * PATCH; i += blockDim.x) {
        int v = i / PATCH, j = i % PATCH;
        int sidx = p * STRIDEP + j;
        if (sidx > SEQL - 1) sidx = SEQL - 1;
        float x = tokens[((size_t)b * SEQL + sidx) * NVAR + v];
        int bv = b * NVAR + v;
        sp[i] = (x - g_mean[bv]) / g_std[bv];
    }
    __syncthreads();
    for (int o = threadIdx.x; o < NVAR * DIM; o += blockDim.x) {
        int v = o >> 9;
        int d = o & (DIM - 1);
        float acc = pe_b[d];
#pragma unroll
        for (int j = 0; j < PATCH; j++) acc += sp[v * PATCH + j] * pe_w[j * DIM + d];
        size_t t = (size_t)(b * PNUM + p) * NVAR + v;
        g_hA[t * DIM + d] = acc;
    }
}

// ---------------- rmsnorm -> fp32 ----------------
__global__ void rmsnorm_kernel(int src_sel, int dst_sel, const float* __restrict__ w) {
    const float* src = g_bufs[src_sel];
    float* dst = g_bufs[dst_sel];
    size_t row = blockIdx.x;
    float4 xv = ((const float4*)(src + row * DIM))[threadIdx.x];
    float ss = xv.x * xv.x + xv.y * xv.y + xv.z * xv.z + xv.w * xv.w;
    for (int o = 16; o; o >>= 1) ss += __shfl_xor_sync(0xffffffffu, ss, o);
    __shared__ float sh[4];
    if ((threadIdx.x & 31) == 0) sh[threadIdx.x >> 5] = ss;
    __syncthreads();
    ss = sh[0] + sh[1] + sh[2] + sh[3];
    float r = rsqrtf(ss * (1.0f / DIM) + EPSR);
    float4 wv = ((const float4*)w)[threadIdx.x];
    float4 o4 = make_float4(xv.x * r * wv.x, xv.y * r * wv.y, xv.z * r * wv.z, xv.w * r * wv.w);
    ((float4*)(dst + row * DIM))[threadIdx.x] = o4;
}

__device__ __forceinline__ void split_store4(__nv_bfloat16* dh, __nv_bfloat16* dl,
                                             float a, float b, float c, float d) {
    __nv_bfloat16 h0 = __float2bfloat16(a), h1 = __float2bfloat16(b);
    __nv_bfloat16 h2 = __float2bfloat16(c), h3 = __float2bfloat16(d);
    __nv_bfloat162 p0; p0.x = h0; p0.y = h1;
    __nv_bfloat162 p1; p1.x = h2; p1.y = h3;
    ((__nv_bfloat162*)dh)[0] = p0;
    ((__nv_bfloat162*)dh)[1] = p1;
    __nv_bfloat162 q0, q1;
    q0.x = __float2bfloat16(a - __bfloat162float(h0));
    q0.y = __float2bfloat16(b - __bfloat162float(h1));
    q1.x = __float2bfloat16(c - __bfloat162float(h2));
    q1.y = __float2bfloat16(d - __bfloat162float(h3));
    ((__nv_bfloat162*)dl)[0] = q0;
    ((__nv_bfloat162*)dl)[1] = q1;
}

// ---------------- rmsnorm -> bf16 hi/lo ----------------
__global__ void rmsnorm16_kernel(int src_sel, int pair, const float* __restrict__ w) {
    const float* src = g_bufs[src_sel];
    __nv_bfloat16* dh = g_bufs16[pair * 2];
    __nv_bfloat16* dl = g_bufs16[pair * 2 + 1];
    size_t row = blockIdx.x;
    float4 xv = ((const float4*)(src + row * DIM))[threadIdx.x];
    float ss = xv.x * xv.x + xv.y * xv.y + xv.z * xv.z + xv.w * xv.w;
    for (int o = 16; o; o >>= 1) ss += __shfl_xor_sync(0xffffffffu, ss, o);
    __shared__ float sh[4];
    if ((threadIdx.x & 31) == 0) sh[threadIdx.x >> 5] = ss;
    __syncthreads();
    ss = sh[0] + sh[1] + sh[2] + sh[3];
    float r = rsqrtf(ss * (1.0f / DIM) + EPSR);
    float4 wv = ((const float4*)w)[threadIdx.x];
    split_store4(dh + row * DIM + threadIdx.x * 4, dl + row * DIM + threadIdx.x * 4,
                 xv.x * r * wv.x, xv.y * r * wv.y, xv.z * r * wv.z, xv.w * r * wv.w);
}

// ---------------- transition: rmsnorm(norm_w) + remap rel->enc ----------------
__global__ void transition_kernel(const float* __restrict__ w) {
    size_t t = blockIdx.x;
    int v = (int)(t % NVAR);
    int bp = (int)(t / NVAR);
    int p = bp % PNUM, b = bp / PNUM;
    size_t t2 = (size_t)(b * NVAR + v) * PNUM + p;
    float4 xv = ((const float4*)(g_hA + t * DIM))[threadIdx.x];
    float ss = xv.x * xv.x + xv.y * xv.y + xv.z * xv.z + xv.w * xv.w;
    for (int o = 16; o; o >>= 1) ss += __shfl_xor_sync(0xffffffffu, ss, o);
    __shared__ float sh[4];
    if ((threadIdx.x & 31) == 0) sh[threadIdx.x >> 5] = ss;
    __syncthreads();
    ss = sh[0] + sh[1] + sh[2] + sh[3];
    float r = rsqrtf(ss * (1.0f / DIM) + EPSR);
    float4 wv = ((const float4*)w)[threadIdx.x];
    float4 o4 = make_float4(xv.x * r * wv.x, xv.y * r * wv.y, xv.z * r * wv.z, xv.w * r * wv.w);
    ((float4*)(g_hB + t2 * DIM))[threadIdx.x] = o4;
}

// ---------------- weight prep: fp32 [K,N] -> bf16 hi/lo [N,K] ----------------
__global__ void wprep_kernel(const float* __restrict__ src, size_t off, int K, int N) {
    __shared__ float t[32][33];
    int k0 = blockIdx.y * 32, n0 = blockIdx.x * 32;
    for (int r = threadIdx.y; r < 32; r += 8)
        t[r][threadIdx.x] = src[(size_t)(k0 + r) * N + n0 + threadIdx.x];
    __syncthreads();
    for (int r = threadIdx.y; r < 32; r += 8) {
        int n = n0 + r, k = k0 + threadIdx.x;
        float x = t[threadIdx.x][r];
        __nv_bfloat16 h = __float2bfloat16(x);
        g_wtH[off + (size_t)n * K + k] = h;
        g_wtL[off + (size_t)n * K + k] = __float2bfloat16(x - __bfloat162float(h));
    }
}

// ---------------- GEMM: C[M,N] = A[M,K] @ Wt[N,K]^T (+residual), 3xBF16 ----------------
#define TM 128
#define TN 128
#define KC 64
#define SM_HDR   1024
#define SM_STAGE 65536
#define SM_AH 0
#define SM_AL 16384
#define SM_BH 32768
#define SM_BL 49152
#define GEMM_SMEM (SM_HDR + 2 * SM_STAGE)

__global__ void __launch_bounds__(256) tc_gemm(int a_sel, size_t w_off,
                                               int c_sel, int r_sel,
                                               int M, int N, int K) {
    extern __shared__ __align__(1024) char smem[];
    uint32_t sb = smem_u32(smem);
    int tid = threadIdx.x, wid = tid >> 5, lane = tid & 31;

    const __nv_bfloat16* Ah = g_bufs16[a_sel * 2];
    const __nv_bfloat16* Al = g_bufs16[a_sel * 2 + 1];
    const __nv_bfloat16* Bh = g_wtH + w_off;
    const __nv_bfloat16* Bl = g_wtL + w_off;
    int bm = blockIdx.y * TM;
    int bn = blockIdx.x * TN;
    const int nch = K / KC;

    auto load_chunk = [&](int ch) {
        int s = ch & 1;
        uint32_t base = sb + SM_HDR + s * SM_STAGE;
        const __nv_bfloat16* sAh = Ah + (size_t)bm * K + ch * KC;
        const __nv_bfloat16* sAl = Al + (size_t)bm * K + ch * KC;
        const __nv_bfloat16* sBh = Bh + (size_t)bn * K + ch * KC;
        const __nv_bfloat16* sBl = Bl + (size_t)bn * K + ch * KC;
        for (int idx = tid; idx < 128 * 8; idx += 256) {
            int r = idx >> 3, c = idx & 7;
            uint32_t sw = SMEM_SWIZZLE_128B(r * 128 + c * 16);
            cp16(base + SM_AH + sw, sAh + (size_t)r * K + c * 8);
            cp16(base + SM_AL + sw, sAl + (size_t)r * K + c * 8);
            cp16(base + SM_BH + sw, sBh + (size_t)r * K + c * 8);
            cp16(base + SM_BL + sw, sBl + (size_t)r * K + c * 8);
        }
        cp_commit();
    };

#if HAS_TCGEN05
    if (wid == 0) TCGEN05_ALLOC(sb, TN);
    if (tid == 0) { MBARRIER_INIT(sb + 16, 1); MBARRIER_INIT(sb + 24, 1); }
    __syncthreads();
    uint32_t tmem;
    asm volatile("ld.shared.b32 %0, [%1];" : "=r"(tmem) : "r"(sb));

    load_chunk(0);
    load_chunk(1);

    const uint32_t idesc = (1u << 4) | (1u << 7) | (1u << 10) | ((TN / 8) << 17) | ((TM / 16) << 24);
    int ph[2] = {0, 0};

    for (int ch = 0; ch < nch; ch++) {
        int s = ch & 1;
        if (ch + 1 < nch) asm volatile("cp.async.wait_group 1;" ::: "memory");
        else              asm volatile("cp.async.wait_group 0;" ::: "memory");
        __syncthreads();
        if (tid == 0) {
            asm volatile("fence.proxy.async.shared::cta;" ::: "memory");
            uint32_t base = sb + SM_HDR + s * SM_STAGE;
            unsigned long long dAh = MAKE_SMEM_DESC(base + SM_AH);
            unsigned long long dAl = MAKE_SMEM_DESC(base + SM_AL);
            unsigned long long dBh = MAKE_SMEM_DESC(base + SM_BH);
            unsigned long long dBl = MAKE_SMEM_DESC(base + SM_BL);
#pragma unroll
            for (int k = 0; k < 4; k++) {
                mma_bf16_ss(tmem, dAh + 2 * k, dBh + 2 * k, idesc, !(ch == 0 && k == 0));
                mma_bf16_ss(tmem, dAl + 2 * k, dBh + 2 * k, idesc, true);
                mma_bf16_ss(tmem, dAh + 2 * k, dBl + 2 * k, idesc, true);
            }
            TCGEN05_COMMIT(sb + 16 + 8 * s);
        }
        if (ch + 2 < nch) {
            MBARRIER_WAIT_PARITY(sb + 16 + 8 * s, ph[s]);
            ph[s] ^= 1;
            load_chunk(ch + 2);
        }
    }
    int sl = (nch - 1) & 1;
    MBARRIER_WAIT_PARITY(sb + 16 + 8 * sl, ph[sl]);
    TCGEN05_FENCE_AFTER();

    float* C = g_bufs[c_sel];
    const float* R = (r_sel >= 0) ? g_bufs[r_sel] : (const float*)0;
    int cb = (wid >> 2) * 64;
    size_t m = (size_t)bm + (wid & 3) * 32 + lane;
    for (int nb = 0; nb < 64; nb += 32) {
        uint32_t d[32];
        TCGEN05_LD_32X32B_X32(d, tmem + cb + nb);
        TCGEN05_WAIT_LD();
        float* cr = C + m * N + bn + cb + nb;
        if (R) {
            const float* rr = R + m * N + bn + cb + nb;
#pragma unroll
            for (int j = 0; j < 8; j++) {
                float4 rv = ((const float4*)rr)[j];
                float4 ov = make_float4(__uint_as_float(d[4 * j]) + rv.x,
                                        __uint_as_float(d[4 * j + 1]) + rv.y,
                                        __uint_as_float(d[4 * j + 2]) + rv.z,
                                        __uint_as_float(d[4 * j + 3]) + rv.w);
                ((float4*)cr)[j] = ov;
            }
        } else {
#pragma unroll
            for (int j = 0; j < 8; j++) {
                float4 ov = make_float4(__uint_as_float(d[4 * j]),
                                        __uint_as_float(d[4 * j + 1]),
                                        __uint_as_float(d[4 * j + 2]),
                                        __uint_as_float(d[4 * j + 3]));
                ((float4*)cr)[j] = ov;
            }
        }
    }
    TCGEN05_FENCE_BEFORE();
    __syncthreads();
    if (wid == 0) TCGEN05_DEALLOC(tmem, TN);
#else
    // ---- mma.sync fallback: 8 warps as 2(m) x 4(n); warp tile 64x32 ----
    int wm = wid >> 2, wn = wid & 3;
    float acc[4][4][4];
#pragma unroll
    for (int i = 0; i < 4; i++)
#pragma unroll
        for (int j = 0; j < 4; j++)
#pragma unroll
            for (int q = 0; q < 4; q++) acc[i][j][q] = 0.f;

    load_chunk(0);
    load_chunk(1);

    for (int ch = 0; ch < nch; ch++) {
        int s = ch & 1;
        if (ch + 1 < nch) asm volatile("cp.async.wait_group 1;" ::: "memory");
        else              asm volatile("cp.async.wait_group 0;" ::: "memory");
        __syncthreads();
        uint32_t base = sb + SM_HDR + s * SM_STAGE;
#pragma unroll
        for (int op = 0; op < 3; op++) {
            uint32_t abase = base + (op == 1 ? (uint32_t)SM_AL : (uint32_t)SM_AH);
            uint32_t bbase = base + (op == 2 ? (uint32_t)SM_BL : (uint32_t)SM_BH);
#pragma unroll
            for (int k16 = 0; k16 < 4; k16++) {
                uint32_t a[4][4];
#pragma unroll
                for (int mt = 0; mt < 4; mt++) {
                    int row = wm * 64 + mt * 16 + (lane & 15);
                    uint32_t off = (uint32_t)row * 128 + k16 * 32 + ((lane >> 4) << 4);
                    ldmx4(a[mt], abase + SMEM_SWIZZLE_128B(off));
                }
                uint32_t bt[4][2];
#pragma unroll
                for (int p = 0; p < 2; p++) {
                    int row = wn * 32 + p * 16 + (lane & 15);
                    uint32_t off = (uint32_t)row * 128 + k16 * 32 + ((lane >> 4) << 4);
                    uint32_t t4[4];
                    ldmx4(t4, bbase + SMEM_SWIZZLE_128B(off));
                    bt[p * 2][0] = t4[0]; bt[p * 2 + 1][0] = t4[1];
                    bt[p * 2][1] = t4[2]; bt[p * 2 + 1][1] = t4[3];
                }
#pragma unroll
                for (int mt = 0; mt < 4; mt++)
#pragma unroll
                    for (int nt = 0; nt < 4; nt++)
                        mma16816(acc[mt][nt], a[mt], bt[nt]);
            }
        }
        __syncthreads();
        if (ch + 2 < nch) load_chunk(ch + 2);
    }

    float* C = g_bufs[c_sel];
    const float* R = (r_sel >= 0) ? g_bufs[r_sel] : (const float*)0;
#pragma unroll
    for (int mt = 0; mt < 4; mt++) {
#pragma unroll
        for (int nt = 0; nt < 4; nt++) {
            int r0 = bm + wm * 64 + mt * 16 + (lane >> 2);
            int nn = bn + wn * 32 + nt * 8 + (lane & 3) * 2;
            float2 v0 = make_float2(acc[mt][nt][0], acc[mt][nt][1]);
            float2 v1 = make_float2(acc[mt][nt][2], acc[mt][nt][3]);
            if (R) {
                float2 q0 = *(const float2*)(R + (size_t)r0 * N + nn);
                float2 q1 = *(const float2*)(R + (size_t)(r0 + 8) * N + nn);
                v0.x += q0.x; v0.y += q0.y;
                v1.x += q1.x; v1.y += q1.y;
            }
            *(float2*)(C + (size_t)r0 * N + nn) = v0;
            *(float2*)(C + (size_t)(r0 + 8) * N + nn) = v1;
        }
    }
#endif
}

// ---------------- attention (writes bf16 hi/lo pair 1) ----------------
__global__ void __launch_bounds__(256) attention_kernel(int S, int rope_mask) {
    __shared__ __align__(16) float s_a[PNUM * HDIM];
    __shared__ __align__(16) float s_k[PNUM * HDIM];
    __shared__ float s_sc[PNUM * PNUM];
    int h = blockIdx.x;
    int bb = blockIdx.y;
    size_t base = (size_t)bb * S * DIM + h * HDIM;
    int tid = threadIdx.x;

    for (int i = tid; i < S * HDIM; i += 256) {
        int s = i / HDIM, d = i % HDIM;
        s_a[i] = g_q[base + (size_t)s * DIM + d];
        s_k[i] = g_k[base + (size_t)s * DIM + d];
    }
    __syncthreads();

    if (rope_mask) {
        for (int i = tid; i < S * (HDIM / 2); i += 256) {
            int s = i / (HDIM / 2), ii = i % (HDIM / 2);
            float c = g_cos[s * (HDIM / 2) + ii];
            float sn = g_sin[s * (HDIM / 2) + ii];
            float xr = s_a[s * HDIM + 2 * ii], xi = s_a[s * HDIM + 2 * ii + 1];
            s_a[s * HDIM + 2 * ii]     = xr * c - xi * sn;
            s_a[s * HDIM + 2 * ii + 1] = xr * sn + xi * c;
            xr = s_k[s * HDIM + 2 * ii]; xi = s_k[s * HDIM + 2 * ii + 1];
            s_k[s * HDIM + 2 * ii]     = xr * c - xi * sn;
            s_k[s * HDIM + 2 * ii + 1] = xr * sn + xi * c;
        }
        __syncthreads();
    }

    const float scale = 0.125f;
    for (int idx = tid; idx < S * S; idx += 256) {
        int i2 = idx / S, j = idx % S;
        if (rope_mask && j > i2) { s_sc[idx] = -INFINITY; continue; }
        const float4* qr = (const float4*)(s_a + i2 * HDIM);
        const float4* kr = (const float4*)(s_k + j * HDIM);
        float acc = 0.f;
#pragma unroll
        for (int d4 = 0; d4 < HDIM / 4; d4++) {
            float4 a = qr[d4], b = kr[d4];
            acc += a.x * b.x + a.y * b.y + a.z * b.z + a.w * b.w;
        }
        s_sc[idx] = acc * scale;
    }
    __syncthreads();

    int tpr = 256 / S;
    int row = tid / tpr, g = tid % tpr;
    float m = -INFINITY;
    for (int j = g; j < S; j += tpr) m = fmaxf(m, s_sc[row * S + j]);
    for (int off = tpr >> 1; off; off >>= 1) m = fmaxf(m, __shfl_xor_sync(0xffffffffu, m, off));
    float sum = 0.f;
    for (int j = g; j < S; j += tpr) {
        float e = __expf(s_sc[row * S + j] - m);
        s_sc[row * S + j] = e;
        sum += e;
    }
    for (int off = tpr >> 1; off; off >>= 1) sum += __shfl_xor_sync(0xffffffffu, sum, off);
    float inv = 1.0f / sum;
    for (int j = g; j < S; j += tpr) s_sc[row * S + j] *= inv;
    __syncthreads();

    for (int i = tid; i < S * HDIM; i += 256) {
        int s = i / HDIM, d = i % HDIM;
        s_a[i] = g_v[base + (size_t)s * DIM + d];
    }
    __syncthreads();

    for (int idx = tid; idx < S * HDIM; idx += 256) {
        int i2 = idx / HDIM, d = idx % HDIM;
        float acc = 0.f;
        for (int j = 0; j < S; j++) acc += s_sc[i2 * S + j] * s_a[j * HDIM + d];
        size_t o = base + (size_t)i2 * DIM + d;
        __nv_bfloat16 hh = __float2bfloat16(acc);
        g_att16H[o] = hh;
        g_att16L[o] = __float2bfloat16(acc - __bfloat162float(hh));
    }
}

// ---------------- silu(f1)*f3 -> bf16 hi/lo pair 2 ----------------
__global__ void silu16_kernel() {
    size_t i = ((size_t)blockIdx.x * blockDim.x + threadIdx.x) * 4;
    float4 a = *(const float4*)(g_f1 + i);
    float4 b = *(const float4*)(g_f3 + i);
    float x0 = a.x / (1.f + __expf(-a.x)) * b.x;
    float x1 = a.y / (1.f + __expf(-a.y)) * b.y;
    float x2 = a.z / (1.f + __expf(-a.z)) * b.z;
    float x3 = a.w / (1.f + __expf(-a.w)) * b.w;
    split_store4(g_f116H + i, g_f116L + i, x0, x1, x2, x3);
}

// ---------------- head GEMM ----------------
__global__ void __launch_bounds__(256) head_kernel(const float* __restrict__ Bw,
                                                   const float* __restrict__ bias) {
    int r = blockIdx.x;
    int n0 = blockIdx.y * 8;
    const float* arow = g_hn + (size_t)r * (PNUM * DIM);
    float acc[8] = {0.f, 0.f, 0.f, 0.f, 0.f, 0.f, 0.f, 0.f};
    for (int kidx = threadIdx.x; kidx < PNUM * DIM; kidx += 256) {
        float a = arow[kidx];
        const float* br = Bw + (size_t)kidx * PRED + n0;
#pragma unroll
        for (int j = 0; j < 8; j++) acc[j] += a * br[j];
    }
    __shared__ float sh[8][8];
    int lane = threadIdx.x & 31, wid = threadIdx.x >> 5;
#pragma unroll
    for (int j = 0; j < 8; j++) {
        float v = acc[j];
        for (int off = 16; off; off >>= 1) v += __shfl_xor_sync(0xffffffffu, v, off);
        if (lane == 0) sh[wid][j] = v;
    }
    __syncthreads();
    if (threadIdx.x < 8) {
        float s2 = 0.f;
#pragma unroll
        for (int w = 0; w < 8; w++) s2 += sh[w][threadIdx.x];
        g_z[(size_t)r * PRED + n0 + threadIdx.x] = s2 + bias[n0 + threadIdx.x];
    }
}

__global__ void finalize_kernel(float* __restrict__ out) {
    int i = blockIdx.x * blockDim.x + threadIdx.x;
    if (i >= BSZ * PRED * NVAR) return;
    int v = i % NVAR;
    int bt = i / NVAR;
    int t = bt % PRED;
    int b = bt / PRED;
    int bv = b * NVAR + v;
    out[i] = g_z[(size_t)bv * PRED + t] * g_std[bv] + g_mean[bv];
}

// ---------------- driver ----------------
extern "C" void kernel_launch(void* const* d_in, const int* in_sizes, int n_in,
                              void* d_out, int out_size) {
    const float* in[24];
    for (int i = 0; i < 24 && i < n_in; i++) in[i] = (const float*)d_in[i];

    const float *tokens = in[0], *pe_w = in[1], *pe_b = in[2];
    const float *norm_w, *head_w, *head_b;
    const float* W[2][9];

    if (in_sizes[3] == 512) {
        norm_w = in[3]; head_w = in[4]; head_b = in[5];
        for (int s = 0; s < 2; s++)
            for (int j = 0; j < 9; j++) W[s][j] = in[6 + s * 9 + j];
    } else {
        for (int s = 0; s < 2; s++)
            for (int j = 0; j < 9; j++) W[s][j] = in[3 + s * 9 + j];
        norm_w = in[21]; head_w = in[22]; head_b = in[23];
    }

    cudaFuncSetAttribute(tc_gemm, cudaFuncAttributeMaxDynamicSharedMemorySize, GEMM_SMEM);

    stats_kernel<<<BSZ * NVAR, 128>>>(tokens);
    rope_init_kernel<<<PNUM, HDIM / 2>>>();
    patch_embed_kernel<<<BSZ * PNUM, 256>>>(tokens, pe_w, pe_b);

    for (int s = 0; s < 2; s++) {
        for (int i = 0; i < NLAYER; i++) {
            size_t base = ((size_t)s * NLAYER + i) * WT_LAYER;
            wprep_kernel<<<dim3(DIM / 32, DIM / 32), dim3(32, 8)>>>(W[s][0] + (size_t)i * DIM * DIM, base + OFF_Q, DIM, DIM);
            wprep_kernel<<<dim3(DIM / 32, DIM / 32), dim3(32, 8)>>>(W[s][1] + (size_t)i * DIM * DIM, base + OFF_K, DIM, DIM);
            wprep_kernel<<<dim3(DIM / 32, DIM / 32), dim3(32, 8)>>>(W[s][2] + (size_t)i * DIM * DIM, base + OFF_V, DIM, DIM);
            wprep_kernel<<<dim3(DIM / 32, DIM / 32), dim3(32, 8)>>>(W[s][3] + (size_t)i * DIM * DIM, base + OFF_O, DIM, DIM);
            wprep_kernel<<<dim3(HIDDEN / 32, DIM / 32), dim3(32, 8)>>>(W[s][4] + (size_t)i * DIM * HIDDEN, base + OFF_W1, DIM, HIDDEN);
            wprep_kernel<<<dim3(HIDDEN / 32, DIM / 32), dim3(32, 8)>>>(W[s][6] + (size_t)i * DIM * HIDDEN, base + OFF_W3, DIM, HIDDEN);
            wprep_kernel<<<dim3(DIM / 32, HIDDEN / 32), dim3(32, 8)>>>(W[s][5] + (size_t)i * HIDDEN * DIM, base + OFF_W2, HIDDEN, DIM);
        }
    }

    dim3 gD(DIM / TN, TOK / TM);        // (4, 512)
    dim3 gH(HIDDEN / TN, TOK / TM);     // (12, 512)

    for (int stage = 0; stage < 2; stage++) {
        int S = stage ? PNUM : NVAR;
        int nb = TOK / S;
        int stream_sel = stage ? BUF_HB : BUF_HA;
        for (int i = 0; i < NLAYER; i++) {
            size_t base = ((size_t)stage * NLAYER + i) * WT_LAYER;
            const float* an = W[stage][7] + (size_t)i * DIM;
            const float* fn = W[stage][8] + (size_t)i * DIM;

            rmsnorm16_kernel<<<TOK, 128>>>(stream_sel, 0, an);
            tc_gemm<<<gD, 256, GEMM_SMEM>>>(0, base + OFF_Q, BUF_Q, -1, TOK, DIM, DIM);
            tc_gemm<<<gD, 256, GEMM_SMEM>>>(0, base + OFF_K, BUF_K, -1, TOK, DIM, DIM);
            tc_gemm<<<gD, 256, GEMM_SMEM>>>(0, base + OFF_V, BUF_V, -1, TOK, DIM, DIM);
            attention_kernel<<<dim3(NHEAD, nb), 256>>>(S, stage);
            tc_gemm<<<gD, 256, GEMM_SMEM>>>(1, base + OFF_O, stream_sel, stream_sel, TOK, DIM, DIM);
            rmsnorm16_kernel<<<TOK, 128>>>(stream_sel, 0, fn);
            tc_gemm<<<gH, 256, GEMM_SMEM>>>(0, base + OFF_W1, BUF_F1, -1, TOK, HIDDEN, DIM);
            tc_gemm<<<gH, 256, GEMM_SMEM>>>(0, base + OFF_W3, BUF_F3, -1, TOK, HIDDEN, DIM);
            silu16_kernel<<<(int)(((size_t)TOK * HIDDEN) / 1024), 256>>>();
            tc_gemm<<<gD, 256, GEMM_SMEM>>>(2, base + OFF_W2, stream_sel, stream_sel, TOK, DIM, HIDDEN);
        }
        if (stage == 0) transition_kernel<<<TOK, 128>>>(norm_w);
    }

    rmsnorm_kernel<<<TOK, 128>>>(BUF_HB, BUF_HN, norm_w);
    head_kernel<<<dim3(BSZ * NVAR, PRED / 8), 256>>>(head_w, head_b);
    finalize_kernel<<<(BSZ * PRED * NVAR + 255) / 256, 256>>>((float*)d_out);
    (void)out_size; (void)n_in;
}

// round 5
// speedup vs baseline: 2.8895x; 1.1271x over previous
#include <cuda_runtime.h>
#include <cuda_bf16.h>
#include <math.h>
#include <stdint.h>

// ---------------- problem constants ----------------
#define BSZ    32
#define SEQL   512
#define NVAR   32
#define PATCH  16
#define STRIDEP 8
#define DIM    512
#define NHEAD  8
#define NLAYER 4
#define HDIM   64
#define HIDDEN 1536
#define PNUM   64
#define PRED   96
#define TOK    65536
#define EPSR   1e-5f

#if defined(__CUDA_ARCH_FEAT_SM103_ALL) || defined(__CUDA_ARCH_FEAT_SM100_ALL)
#define HAS_TCGEN05 1
#else
#define HAS_TCGEN05 0
#endif

// ---------------- helpers ----------------
#define SMEM_SWIZZLE_128B(o) ((uint32_t)(o) ^ ((((uint32_t)(o)) >> 3) & 0x70))
#define SMEM_DESC_BASE_SW128_C ((2ULL << 61) | (1ULL << 46) | (64ULL << 32) | (1ULL << 16))
#define MAKE_SMEM_DESC(a) (SMEM_DESC_BASE_SW128_C | ((unsigned long long)(((a) >> 4) & 0x3FFF)))

static __device__ __forceinline__ uint32_t smem_u32(const void* p) {
    uint32_t a;
    asm("{ .reg .u64 t; cvta.to.shared.u64 t, %1; cvt.u32.u64 %0, t; }" : "=r"(a) : "l"(p));
    return a;
}

__device__ __forceinline__ void cp16(uint32_t dst, const void* src) {
    asm volatile("cp.async.cg.shared.global [%0], [%1], 16;" :: "r"(dst), "l"(src) : "memory");
}
__device__ __forceinline__ void cp_commit() { asm volatile("cp.async.commit_group;" ::: "memory"); }

#if HAS_TCGEN05
#define TCGEN05_ALLOC(smem_result_addr, nCols) \
    asm volatile("tcgen05.alloc.cta_group::1.sync.aligned.shared::cta.b32 [%0], %1;" \
        :: "r"((uint32_t)(smem_result_addr)), "r"((uint32_t)(nCols)) : "memory")
#define TCGEN05_DEALLOC(tmem_addr, nCols) \
    asm volatile("tcgen05.dealloc.cta_group::1.sync.aligned.b32 %0, %1;" \
        :: "r"(tmem_addr), "r"((uint32_t)(nCols)))
#define TCGEN05_COMMIT(mbar_smem_addr) \
    asm volatile("tcgen05.commit.cta_group::1.mbarrier::arrive::one.shared::cluster.b64 [%0];" \
        :: "r"((uint32_t)(mbar_smem_addr)) : "memory")
#define TCGEN05_WAIT_LD() asm volatile("tcgen05.wait::ld.sync.aligned;" ::: "memory")
#define TCGEN05_FENCE_BEFORE() asm volatile("tcgen05.fence::before_thread_sync;" ::: "memory")
#define TCGEN05_FENCE_AFTER()  asm volatile("tcgen05.fence::after_thread_sync;" ::: "memory")

#define MBARRIER_INIT(mbar_smem_addr, count) \
    asm volatile("mbarrier.init.shared.b64 [%0], %1;" \
        :: "r"((uint32_t)(mbar_smem_addr)), "r"((uint32_t)(count)) : "memory")

#define MBARRIER_WAIT_PARITY(mbar_smem_addr, phase_parity) do { \
    uint32_t _mbar = (uint32_t)(mbar_smem_addr); \
    uint32_t _parity = (uint32_t)(phase_parity); \
    uint32_t _done; \
    asm volatile( \
        "{\n\t" \
        ".reg .pred p;\n\t" \
        "mbarrier.try_wait.parity.acquire.cta.shared::cta.b64 p, [%1], %2;\n\t" \
        "selp.b32 %0, 1, 0, p;\n\t" \
        "}" \
        : "=r"(_done) : "r"(_mbar), "r"(_parity) : "memory"); \
    if (!_done) { \
        asm volatile( \
            "{\n\t" \
            ".reg .pred P1;\n\t" \
            "WAIT_LOOP_%=:\n\t" \
            "mbarrier.try_wait.parity.acquire.cta.shared::cta.b64 P1, [%0], %1, 0x989680;\n\t" \
            "@P1 bra.uni WAIT_DONE_%=;\n\t" \
            "bra.uni WAIT_LOOP_%=;\n\t" \
            "WAIT_DONE_%=:\n\t" \
            "}" \
            :: "r"(_mbar), "r"(_parity) : "memory"); \
    } \
} while(0)

#define TCGEN05_LD_32X32B_X32(r, tmem_addr) \
    asm volatile( \
        "tcgen05.ld.sync.aligned.32x32b.x32.b32 " \
        "{%0, %1, %2, %3, %4, %5, %6, %7, " \
        " %8, %9, %10, %11, %12, %13, %14, %15, " \
        " %16, %17, %18, %19, %20, %21, %22, %23, " \
        " %24, %25, %26, %27, %28, %29, %30, %31}, [%32];" \
        : "=r"((r)[0]),  "=r"((r)[1]),  "=r"((r)[2]),  "=r"((r)[3]), \
          "=r"((r)[4]),  "=r"((r)[5]),  "=r"((r)[6]),  "=r"((r)[7]), \
          "=r"((r)[8]),  "=r"((r)[9]),  "=r"((r)[10]), "=r"((r)[11]), \
          "=r"((r)[12]), "=r"((r)[13]), "=r"((r)[14]), "=r"((r)[15]), \
          "=r"((r)[16]), "=r"((r)[17]), "=r"((r)[18]), "=r"((r)[19]), \
          "=r"((r)[20]), "=r"((r)[21]), "=r"((r)[22]), "=r"((r)[23]), \
          "=r"((r)[24]), "=r"((r)[25]), "=r"((r)[26]), "=r"((r)[27]), \
          "=r"((r)[28]), "=r"((r)[29]), "=r"((r)[30]), "=r"((r)[31]) \
        : "r"(tmem_addr))

__device__ __forceinline__ void mma_bf16_ss(uint32_t d, unsigned long long ad,
                                            unsigned long long bd, uint32_t idesc, bool acc) {
    uint32_t e = acc ? 1u : 0u;
    asm volatile(
        "{\n\t"
        ".reg .pred p;\n\t"
        "setp.ne.u32 p, %5, 0;\n\t"
        "tcgen05.mma.cta_group::1.kind::f16 [%0], %1, %2, %3, {%4, %4, %4, %4}, p;\n\t"
        "}"
        :: "r"(d), "l"(ad), "l"(bd), "r"(idesc), "r"(0u), "r"(e)
        : "memory");
}
#else
__device__ __forceinline__ void ldmx4(uint32_t* r, uint32_t addr) {
    asm volatile("ldmatrix.sync.aligned.m8n8.x4.shared.b16 {%0,%1,%2,%3}, [%4];"
        : "=r"(r[0]), "=r"(r[1]), "=r"(r[2]), "=r"(r[3]) : "r"(addr));
}
__device__ __forceinline__ void mma16816(float* c, const uint32_t* a, const uint32_t* b) {
    asm volatile("mma.sync.aligned.m16n8k16.row.col.f32.bf16.bf16.f32 "
        "{%0,%1,%2,%3},{%4,%5,%6,%7},{%8,%9},{%0,%1,%2,%3};"
        : "+f"(c[0]), "+f"(c[1]), "+f"(c[2]), "+f"(c[3])
        : "r"(a[0]), "r"(a[1]), "r"(a[2]), "r"(a[3]), "r"(b[0]), "r"(b[1]));
}
#endif

// ---------------- device scratch ----------------
__device__ float g_mean[BSZ * NVAR];
__device__ float g_std[BSZ * NVAR];
__device__ float g_cos[PNUM * (HDIM / 2)];
__device__ float g_sin[PNUM * (HDIM / 2)];

__device__ __align__(256) float g_hA[(size_t)TOK * DIM];
__device__ __align__(256) float g_hB[(size_t)TOK * DIM];
__device__ __align__(256) float g_hn[(size_t)TOK * DIM];
__device__ __align__(256) float g_qkv[(size_t)TOK * 1536];
__device__ float g_z[BSZ * NVAR * PRED];

#define BUF_HA  0
#define BUF_HB  1
#define BUF_HN  2
#define BUF_QKV 3
__device__ float* g_bufs[4] = {g_hA, g_hB, g_hn, g_qkv};

// bf16 hi/lo activation pairs: 0=hn [TOK,DIM], 1=att [TOK,DIM], 2=f1s [TOK,HIDDEN]
__device__ __align__(256) __nv_bfloat16 g_hn16H[(size_t)TOK * DIM];
__device__ __align__(256) __nv_bfloat16 g_hn16L[(size_t)TOK * DIM];
__device__ __align__(256) __nv_bfloat16 g_att16H[(size_t)TOK * DIM];
__device__ __align__(256) __nv_bfloat16 g_att16L[(size_t)TOK * DIM];
__device__ __align__(256) __nv_bfloat16 g_f116H[(size_t)TOK * HIDDEN];
__device__ __align__(256) __nv_bfloat16 g_f116L[(size_t)TOK * HIDDEN];
__device__ __nv_bfloat16* g_bufs16[6] = {g_hn16H, g_hn16L, g_att16H, g_att16L, g_f116H, g_f116L};

// transposed weights [N,K] bf16 hi/lo, per layer:
// QKV [1536,512] @0 ; O [512,512] @786432 ; W13 [3072,512] @1048576 ; W2 [512,1536] @2621440
#define OFF_QKV 0
#define OFF_O   786432
#define OFF_W13 1048576
#define OFF_W2  2621440
#define WT_LAYER 3407872
#define WT_TOTAL ((size_t)WT_LAYER * 8)
__device__ __align__(256) __nv_bfloat16 g_wtH[WT_TOTAL];
__device__ __align__(256) __nv_bfloat16 g_wtL[WT_TOTAL];

// ---------------- stats ----------------
__global__ void stats_kernel(const float* __restrict__ tokens) {
    int bv = blockIdx.x;
    int b = bv / NVAR, v = bv % NVAR;
    float s = 0.f, s2 = 0.f;
    for (int t = threadIdx.x; t < SEQL; t += blockDim.x) {
        float x = tokens[((size_t)b * SEQL + t) * NVAR + v];
        s += x; s2 += x * x;
    }
    __shared__ float sh0[128], sh1[128];
    sh0[threadIdx.x] = s; sh1[threadIdx.x] = s2;
    __syncthreads();
    for (int o = 64; o > 0; o >>= 1) {
        if (threadIdx.x < o) { sh0[threadIdx.x] += sh0[threadIdx.x + o]; sh1[threadIdx.x] += sh1[threadIdx.x + o]; }
        __syncthreads();
    }
    if (threadIdx.x == 0) {
        float m = sh0[0] / (float)SEQL;
        float var = sh1[0] / (float)SEQL - m * m;
        if (var < 0.f) var = 0.f;
        g_mean[bv] = m;
        g_std[bv] = sqrtf(var + EPSR);
    }
}

__global__ void rope_init_kernel() {
    int i = threadIdx.x;
    int p = blockIdx.x;
    double inv = pow(10000.0, -((double)(2 * i)) / (double)HDIM);
    double ang = (double)p * inv;
    g_cos[p * (HDIM / 2) + i] = (float)cos(ang);
    g_sin[p * (HDIM / 2) + i] = (float)sin(ang);
}

// ---------------- patch embedding ----------------
__global__ void patch_embed_kernel(const float* __restrict__ tokens,
                                   const float* __restrict__ pe_w,
                                   const float* __restrict__ pe_b) {
    int bp = blockIdx.x;
    int b = bp / PNUM, p = bp % PNUM;
    __shared__ float sp[NVAR * PATCH];
    for (int i = threadIdx.x; i < NVAR * PATCH; i += blockDim.x) {
        int v = i / PATCH, j = i % PATCH;
        int sidx = p * STRIDEP + j;
        if (sidx > SEQL - 1) sidx = SEQL - 1;
        float x = tokens[((size_t)b * SEQL + sidx) * NVAR + v];
        int bv = b * NVAR + v;
        sp[i] = (x - g_mean[bv]) / g_std[bv];
    }
    __syncthreads();
    for (int o = threadIdx.x; o < NVAR * DIM; o += blockDim.x) {
        int v = o >> 9;
        int d = o & (DIM - 1);
        float acc = pe_b[d];
#pragma unroll
        for (int j = 0; j < PATCH; j++) acc += sp[v * PATCH + j] * pe_w[j * DIM + d];
        size_t t = (size_t)(b * PNUM + p) * NVAR + v;
        g_hA[t * DIM + d] = acc;
    }
}

// ---------------- rmsnorm -> fp32 ----------------
__global__ void rmsnorm_kernel(int src_sel, int dst_sel, const float* __restrict__ w) {
    const float* src = g_bufs[src_sel];
    float* dst = g_bufs[dst_sel];
    size_t row = blockIdx.x;
    float4 xv = ((const float4*)(src + row * DIM))[threadIdx.x];
    float ss = xv.x * xv.x + xv.y * xv.y + xv.z * xv.z + xv.w * xv.w;
    for (int o = 16; o; o >>= 1) ss += __shfl_xor_sync(0xffffffffu, ss, o);
    __shared__ float sh[4];
    if ((threadIdx.x & 31) == 0) sh[threadIdx.x >> 5] = ss;
    __syncthreads();
    ss = sh[0] + sh[1] + sh[2] + sh[3];
    float r = rsqrtf(ss * (1.0f / DIM) + EPSR);
    float4 wv = ((const float4*)w)[threadIdx.x];
    float4 o4 = make_float4(xv.x * r * wv.x, xv.y * r * wv.y, xv.z * r * wv.z, xv.w * r * wv.w);
    ((float4*)(dst + row * DIM))[threadIdx.x] = o4;
}

__device__ __forceinline__ void split_store4(__nv_bfloat16* dh, __nv_bfloat16* dl,
                                             float a, float b, float c, float d) {
    __nv_bfloat16 h0 = __float2bfloat16(a), h1 = __float2bfloat16(b);
    __nv_bfloat16 h2 = __float2bfloat16(c), h3 = __float2bfloat16(d);
    __nv_bfloat162 p0; p0.x = h0; p0.y = h1;
    __nv_bfloat162 p1; p1.x = h2; p1.y = h3;
    ((__nv_bfloat162*)dh)[0] = p0;
    ((__nv_bfloat162*)dh)[1] = p1;
    __nv_bfloat162 q0, q1;
    q0.x = __float2bfloat16(a - __bfloat162float(h0));
    q0.y = __float2bfloat16(b - __bfloat162float(h1));
    q1.x = __float2bfloat16(c - __bfloat162float(h2));
    q1.y = __float2bfloat16(d - __bfloat162float(h3));
    ((__nv_bfloat162*)dl)[0] = q0;
    ((__nv_bfloat162*)dl)[1] = q1;
}

__device__ __forceinline__ void split_store2(__nv_bfloat16* dh, __nv_bfloat16* dl,
                                             float a, float b) {
    __nv_bfloat16 h0 = __float2bfloat16(a), h1 = __float2bfloat16(b);
    __nv_bfloat162 p0; p0.x = h0; p0.y = h1;
    *((__nv_bfloat162*)dh) = p0;
    __nv_bfloat162 q0;
    q0.x = __float2bfloat16(a - __bfloat162float(h0));
    q0.y = __float2bfloat16(b - __bfloat162float(h1));
    *((__nv_bfloat162*)dl) = q0;
}

// ---------------- rmsnorm -> bf16 hi/lo ----------------
__global__ void rmsnorm16_kernel(int src_sel, int pair, const float* __restrict__ w) {
    const float* src = g_bufs[src_sel];
    __nv_bfloat16* dh = g_bufs16[pair * 2];
    __nv_bfloat16* dl = g_bufs16[pair * 2 + 1];
    size_t row = blockIdx.x;
    float4 xv = ((const float4*)(src + row * DIM))[threadIdx.x];
    float ss = xv.x * xv.x + xv.y * xv.y + xv.z * xv.z + xv.w * xv.w;
    for (int o = 16; o; o >>= 1) ss += __shfl_xor_sync(0xffffffffu, ss, o);
    __shared__ float sh[4];
    if ((threadIdx.x & 31) == 0) sh[threadIdx.x >> 5] = ss;
    __syncthreads();
    ss = sh[0] + sh[1] + sh[2] + sh[3];
    float r = rsqrtf(ss * (1.0f / DIM) + EPSR);
    float4 wv = ((const float4*)w)[threadIdx.x];
    split_store4(dh + row * DIM + threadIdx.x * 4, dl + row * DIM + threadIdx.x * 4,
                 xv.x * r * wv.x, xv.y * r * wv.y, xv.z * r * wv.z, xv.w * r * wv.w);
}

// ---------------- transition: rmsnorm(norm_w) + remap rel->enc ----------------
__global__ void transition_kernel(const float* __restrict__ w) {
    size_t t = blockIdx.x;
    int v = (int)(t % NVAR);
    int bp = (int)(t / NVAR);
    int p = bp % PNUM, b = bp / PNUM;
    size_t t2 = (size_t)(b * NVAR + v) * PNUM + p;
    float4 xv = ((const float4*)(g_hA + t * DIM))[threadIdx.x];
    float ss = xv.x * xv.x + xv.y * xv.y + xv.z * xv.z + xv.w * xv.w;
    for (int o = 16; o; o >>= 1) ss += __shfl_xor_sync(0xffffffffu, ss, o);
    __shared__ float sh[4];
    if ((threadIdx.x & 31) == 0) sh[threadIdx.x >> 5] = ss;
    __syncthreads();
    ss = sh[0] + sh[1] + sh[2] + sh[3];
    float r = rsqrtf(ss * (1.0f / DIM) + EPSR);
    float4 wv = ((const float4*)w)[threadIdx.x];
    float4 o4 = make_float4(xv.x * r * wv.x, xv.y * r * wv.y, xv.z * r * wv.z, xv.w * r * wv.w);
    ((float4*)(g_hB + t2 * DIM))[threadIdx.x] = o4;
}

// ---------------- weight prep kernels ----------------
__device__ __forceinline__ void wt_write(size_t off, int n, int K, int k, float x) {
    __nv_bfloat16 h = __float2bfloat16(x);
    g_wtH[off + (size_t)n * K + k] = h;
    g_wtL[off + (size_t)n * K + k] = __float2bfloat16(x - __bfloat162float(h));
}

// generic fp32 [K,N] -> bf16 hi/lo [N,K]
__global__ void wprep_kernel(const float* __restrict__ src, size_t off, int K, int N) {
    __shared__ float t[32][33];
    int k0 = blockIdx.y * 32, n0 = blockIdx.x * 32;
    for (int r = threadIdx.y; r < 32; r += 8)
        t[r][threadIdx.x] = src[(size_t)(k0 + r) * N + n0 + threadIdx.x];
    __syncthreads();
    for (int r = threadIdx.y; r < 32; r += 8)
        wt_write(off, n0 + r, K, k0 + threadIdx.x, t[threadIdx.x][r]);
}

// packed QKV: dest rows [0,512)=wq, [512,1024)=wk, [1024,1536)=wv  (each src [512,512])
__global__ void wprep_qkv_kernel(const float* __restrict__ wq, const float* __restrict__ wk,
                                 const float* __restrict__ wv, size_t off) {
    __shared__ float t[32][33];
    int k0 = blockIdx.y * 32, n0 = blockIdx.x * 32;
    const float* src = (n0 < 512) ? wq : (n0 < 1024 ? wk : wv);
    int sc = n0 & 511;
    for (int r = threadIdx.y; r < 32; r += 8)
        t[r][threadIdx.x] = src[(size_t)(k0 + r) * 512 + sc + threadIdx.x];
    __syncthreads();
    for (int r = threadIdx.y; r < 32; r += 8)
        wt_write(off, n0 + r, 512, k0 + threadIdx.x, t[threadIdx.x][r]);
}

// packed W13: dest rows block i of 256: [i*256, i*256+128)=w1 cols [i*128..),
// [i*256+128, (i+1)*256)=w3 cols [i*128..).  src [512, 1536].
__global__ void wprep13_kernel(const float* __restrict__ w1, const float* __restrict__ w3,
                               size_t off) {
    __shared__ float t[32][33];
    int k0 = blockIdx.y * 32, n0 = blockIdx.x * 32;
    int i = n0 >> 8;
    int r0 = n0 & 255;
    const float* src = (r0 < 128) ? w1 : w3;
    int sc = i * 128 + (r0 & 127);
    for (int r = threadIdx.y; r < 32; r += 8)
        t[r][threadIdx.x] = src[(size_t)(k0 + r) * HIDDEN + sc + threadIdx.x];
    __syncthreads();
    for (int r = threadIdx.y; r < 32; r += 8)
        wt_write(off, n0 + r, 512, k0 + threadIdx.x, t[threadIdx.x][r]);
}

// ---------------- GEMM: C[M,N] = A[M,K] @ Wt[N,K]^T, 3xBF16, TN=256 ----------------
// emode 0: fp32 out to g_bufs[c_sel] (+residual r_sel)
// emode 1: silu(f1)*f3 fused (W13 packed layout) -> bf16 hi/lo pair 2
#define TM 128
#define TN 256
#define KC 64
#define SM_HDR   1024
#define SM_STAGE 98304
#define SM_AH 0
#define SM_AL 16384
#define SM_BH 32768
#define SM_BL 65536
#define GEMM_SMEM (SM_HDR + 2 * SM_STAGE)

__global__ void __launch_bounds__(256) tc_gemm(int a_sel, size_t w_off, int emode,
                                               int c_sel, int r_sel,
                                               int M, int N, int K) {
    extern __shared__ __align__(1024) char smem[];
    uint32_t sb = smem_u32(smem);
    int tid = threadIdx.x, wid = tid >> 5, lane = tid & 31;

    const __nv_bfloat16* Ah = g_bufs16[a_sel * 2];
    const __nv_bfloat16* Al = g_bufs16[a_sel * 2 + 1];
    const __nv_bfloat16* Bh = g_wtH + w_off;
    const __nv_bfloat16* Bl = g_wtL + w_off;
    int bm = blockIdx.y * TM;
    int bn = blockIdx.x * TN;
    const int nch = K / KC;

    auto load_chunk = [&](int ch) {
        int s = ch & 1;
        uint32_t base = sb + SM_HDR + s * SM_STAGE;
        const __nv_bfloat16* sAh = Ah + (size_t)bm * K + ch * KC;
        const __nv_bfloat16* sAl = Al + (size_t)bm * K + ch * KC;
        const __nv_bfloat16* sBh = Bh + (size_t)bn * K + ch * KC;
        const __nv_bfloat16* sBl = Bl + (size_t)bn * K + ch * KC;
        for (int idx = tid; idx < TM * 8; idx += 256) {
            int r = idx >> 3, c = idx & 7;
            uint32_t sw = SMEM_SWIZZLE_128B(r * 128 + c * 16);
            cp16(base + SM_AH + sw, sAh + (size_t)r * K + c * 8);
            cp16(base + SM_AL + sw, sAl + (size_t)r * K + c * 8);
        }
        for (int idx = tid; idx < TN * 8; idx += 256) {
            int r = idx >> 3, c = idx & 7;
            uint32_t sw = SMEM_SWIZZLE_128B(r * 128 + c * 16);
            cp16(base + SM_BH + sw, sBh + (size_t)r * K + c * 8);
            cp16(base + SM_BL + sw, sBl + (size_t)r * K + c * 8);
        }
        cp_commit();
    };

#if HAS_TCGEN05
    if (wid == 0) TCGEN05_ALLOC(sb, TN);
    if (tid == 0) { MBARRIER_INIT(sb + 16, 1); MBARRIER_INIT(sb + 24, 1); }
    __syncthreads();
    uint32_t tmem;
    asm volatile("ld.shared.b32 %0, [%1];" : "=r"(tmem) : "r"(sb));

    load_chunk(0);
    load_chunk(1);

    const uint32_t idesc = (1u << 4) | (1u << 7) | (1u << 10) | ((TN / 8) << 17) | ((TM / 16) << 24);
    int ph[2] = {0, 0};

    for (int ch = 0; ch < nch; ch++) {
        int s = ch & 1;
        if (ch + 1 < nch) asm volatile("cp.async.wait_group 1;" ::: "memory");
        else              asm volatile("cp.async.wait_group 0;" ::: "memory");
        __syncthreads();
        if (tid == 0) {
            asm volatile("fence.proxy.async.shared::cta;" ::: "memory");
            uint32_t base = sb + SM_HDR + s * SM_STAGE;
            unsigned long long dAh = MAKE_SMEM_DESC(base + SM_AH);
            unsigned long long dAl = MAKE_SMEM_DESC(base + SM_AL);
            unsigned long long dBh = MAKE_SMEM_DESC(base + SM_BH);
            unsigned long long dBl = MAKE_SMEM_DESC(base + SM_BL);
#pragma unroll
            for (int k = 0; k < 4; k++) {
                mma_bf16_ss(tmem, dAh + 2 * k, dBh + 2 * k, idesc, !(ch == 0 && k == 0));
                mma_bf16_ss(tmem, dAl + 2 * k, dBh + 2 * k, idesc, true);
                mma_bf16_ss(tmem, dAh + 2 * k, dBl + 2 * k, idesc, true);
            }
            TCGEN05_COMMIT(sb + 16 + 8 * s);
        }
        if (ch + 2 < nch) {
            MBARRIER_WAIT_PARITY(sb + 16 + 8 * s, ph[s]);
            ph[s] ^= 1;
            load_chunk(ch + 2);
        }
    }
    int sl = (nch - 1) & 1;
    MBARRIER_WAIT_PARITY(sb + 16 + 8 * sl, ph[sl]);
    TCGEN05_FENCE_AFTER();

    size_t m = (size_t)bm + (wid & 3) * 32 + lane;
    if (emode == 0) {
        float* C = g_bufs[c_sel];
        const float* R = (r_sel >= 0) ? g_bufs[r_sel] : (const float*)0;
        int half = (wid >> 2) * 128;
        for (int nb = 0; nb < 128; nb += 32) {
            uint32_t d[32];
            TCGEN05_LD_32X32B_X32(d, tmem + half + nb);
            TCGEN05_WAIT_LD();
            float* cr = C + m * N + bn + half + nb;
            if (R) {
                const float* rr = R + m * N + bn + half + nb;
#pragma unroll
                for (int j = 0; j < 8; j++) {
                    float4 rv = ((const float4*)rr)[j];
                    float4 ov = make_float4(__uint_as_float(d[4 * j]) + rv.x,
                                            __uint_as_float(d[4 * j + 1]) + rv.y,
                                            __uint_as_float(d[4 * j + 2]) + rv.z,
                                            __uint_as_float(d[4 * j + 3]) + rv.w);
                    ((float4*)cr)[j] = ov;
                }
            } else {
#pragma unroll
                for (int j = 0; j < 8; j++) {
                    float4 ov = make_float4(__uint_as_float(d[4 * j]),
                                            __uint_as_float(d[4 * j + 1]),
                                            __uint_as_float(d[4 * j + 2]),
                                            __uint_as_float(d[4 * j + 3]));
                    ((float4*)cr)[j] = ov;
                }
            }
        }
    } else {
        // silu(f1)*f3 -> bf16 hi/lo pair 2.  TMEM cols [0,128)=f1, [128,256)=f3.
        int qd = (wid >> 2) * 64;
        uint32_t f1a[32], f1b[32], f3a[32], f3b[32];
        TCGEN05_LD_32X32B_X32(f1a, tmem + qd);
        TCGEN05_LD_32X32B_X32(f1b, tmem + qd + 32);
        TCGEN05_LD_32X32B_X32(f3a, tmem + 128 + qd);
        TCGEN05_LD_32X32B_X32(f3b, tmem + 128 + qd + 32);
        TCGEN05_WAIT_LD();
        size_t ob = m * HIDDEN + (bn >> 8) * 128 + qd;
#pragma unroll
        for (int j = 0; j < 32; j += 2) {
            float x0 = __uint_as_float(f1a[j]),     y0 = __uint_as_float(f3a[j]);
            float x1 = __uint_as_float(f1a[j + 1]), y1 = __uint_as_float(f3a[j + 1]);
            float o0 = x0 / (1.f + __expf(-x0)) * y0;
            float o1 = x1 / (1.f + __expf(-x1)) * y1;
            split_store2(g_f116H + ob + j, g_f116L + ob + j, o0, o1);
        }
#pragma unroll
        for (int j = 0; j < 32; j += 2) {
            float x0 = __uint_as_float(f1b[j]),     y0 = __uint_as_float(f3b[j]);
            float x1 = __uint_as_float(f1b[j + 1]), y1 = __uint_as_float(f3b[j + 1]);
            float o0 = x0 / (1.f + __expf(-x0)) * y0;
            float o1 = x1 / (1.f + __expf(-x1)) * y1;
            split_store2(g_f116H + ob + 32 + j, g_f116L + ob + 32 + j, o0, o1);
        }
    }
    TCGEN05_FENCE_BEFORE();
    __syncthreads();
    if (wid == 0) TCGEN05_DEALLOC(tmem, TN);
#else
    // ---- mma.sync fallback: 8 warps as 2(m) x 4(n); warp tile 64x64 ----
    int wm = wid >> 2, wn = wid & 3;
    float acc[4][8][4];
#pragma unroll
    for (int i = 0; i < 4; i++)
#pragma unroll
        for (int j = 0; j < 8; j++)
#pragma unroll
            for (int q = 0; q < 4; q++) acc[i][j][q] = 0.f;

    load_chunk(0);
    load_chunk(1);

    for (int ch = 0; ch < nch; ch++) {
        int s = ch & 1;
        if (ch + 1 < nch) asm volatile("cp.async.wait_group 1;" ::: "memory");
        else              asm volatile("cp.async.wait_group 0;" ::: "memory");
        __syncthreads();
        uint32_t base = sb + SM_HDR + s * SM_STAGE;
#pragma unroll
        for (int op = 0; op < 3; op++) {
            uint32_t abase = base + (op == 1 ? (uint32_t)SM_AL : (uint32_t)SM_AH);
            uint32_t bbase = base + (op == 2 ? (uint32_t)SM_BL : (uint32_t)SM_BH);
#pragma unroll
            for (int k16 = 0; k16 < 4; k16++) {
                uint32_t a[4][4];
#pragma unroll
                for (int mt = 0; mt < 4; mt++) {
                    int row = wm * 64 + mt * 16 + (lane & 15);
                    uint32_t off = (uint32_t)row * 128 + k16 * 32 + ((lane >> 4) << 4);
                    ldmx4(a[mt], abase + SMEM_SWIZZLE_128B(off));
                }
                uint32_t bt[8][2];
#pragma unroll
                for (int p = 0; p < 4; p++) {
                    int row = wn * 64 + p * 16 + (lane & 15);
                    uint32_t off = (uint32_t)row * 128 + k16 * 32 + ((lane >> 4) << 4);
                    uint32_t t4[4];
                    ldmx4(t4, bbase + SMEM_SWIZZLE_128B(off));
                    bt[p * 2][0] = t4[0]; bt[p * 2 + 1][0] = t4[1];
                    bt[p * 2][1] = t4[2]; bt[p * 2 + 1][1] = t4[3];
                }
#pragma unroll
                for (int mt = 0; mt < 4; mt++)
#pragma unroll
                    for (int nt = 0; nt < 8; nt++)
                        mma16816(acc[mt][nt], a[mt], bt[nt]);
            }
        }
        __syncthreads();
        if (ch + 2 < nch) load_chunk(ch + 2);
    }
    __syncthreads();

    if (emode == 0) {
        float* C = g_bufs[c_sel];
        const float* R = (r_sel >= 0) ? g_bufs[r_sel] : (const float*)0;
#pragma unroll
        for (int mt = 0; mt < 4; mt++) {
#pragma unroll
            for (int nt = 0; nt < 8; nt++) {
                int r0 = bm + wm * 64 + mt * 16 + (lane >> 2);
                int nn = bn + wn * 64 + nt * 8 + (lane & 3) * 2;
                float2 v0 = make_float2(acc[mt][nt][0], acc[mt][nt][1]);
                float2 v1 = make_float2(acc[mt][nt][2], acc[mt][nt][3]);
                if (R) {
                    float2 q0 = *(const float2*)(R + (size_t)r0 * N + nn);
                    float2 q1 = *(const float2*)(R + (size_t)(r0 + 8) * N + nn);
                    v0.x += q0.x; v0.y += q0.y;
                    v1.x += q1.x; v1.y += q1.y;
                }
                *(float2*)(C + (size_t)r0 * N + nn) = v0;
                *(float2*)(C + (size_t)(r0 + 8) * N + nn) = v1;
            }
        }
    } else {
        // stage f3 half (cols 128..255) through smem, then warps owning f1 fuse.
        float* sf = (float*)(smem + SM_HDR);   // [128][128] fp32
        if (wn >= 2) {
#pragma unroll
            for (int mt = 0; mt < 4; mt++) {
#pragma unroll
                for (int nt = 0; nt < 8; nt++) {
                    int rl = wm * 64 + mt * 16 + (lane >> 2);
                    int c2 = (wn - 2) * 64 + nt * 8 + (lane & 3) * 2;
                    *(float2*)(sf + (size_t)rl * 128 + c2) = make_float2(acc[mt][nt][0], acc[mt][nt][1]);
                    *(float2*)(sf + (size_t)(rl + 8) * 128 + c2) = make_float2(acc[mt][nt][2], acc[mt][nt][3]);
                }
            }
        }
        __syncthreads();
        if (wn < 2) {
            size_t cb = (size_t)(bn >> 8) * 128;
#pragma unroll
            for (int mt = 0; mt < 4; mt++) {
#pragma unroll
                for (int nt = 0; nt < 8; nt++) {
                    int rl = wm * 64 + mt * 16 + (lane >> 2);
                    int c = wn * 64 + nt * 8 + (lane & 3) * 2;
#pragma unroll
                    for (int hh = 0; hh < 2; hh++) {
                        int r = rl + hh * 8;
                        float x0 = acc[mt][nt][hh * 2], x1 = acc[mt][nt][hh * 2 + 1];
                        float y0 = sf[(size_t)r * 128 + c], y1 = sf[(size_t)r * 128 + c + 1];
                        float o0 = x0 / (1.f + __expf(-x0)) * y0;
                        float o1 = x1 / (1.f + __expf(-x1)) * y1;
                        size_t ob = (size_t)(bm + r) * HIDDEN + cb + c;
                        split_store2(g_f116H + ob, g_f116L + ob, o0, o1);
                    }
                }
            }
        }
    }
#endif
}

// ---------------- attention: reads g_qkv [TOK,1536], writes bf16 pair 1 ----------------
__global__ void __launch_bounds__(256) attention_kernel(int S, int rope_mask) {
    __shared__ __align__(16) float s_a[PNUM * HDIM];
    __shared__ __align__(16) float s_k[PNUM * HDIM];
    __shared__ float s_sc[PNUM * PNUM];
    int h = blockIdx.x;
    int bb = blockIdx.y;
    int tid = threadIdx.x;
    size_t rowbase = (size_t)bb * S;

    for (int i = tid; i < S * HDIM; i += 256) {
        int s = i / HDIM, d = i % HDIM;
        size_t rb = (rowbase + s) * 1536 + h * HDIM + d;
        s_a[i] = g_qkv[rb];
        s_k[i] = g_qkv[rb + 512];
    }
    __syncthreads();

    if (rope_mask) {
        for (int i = tid; i < S * (HDIM / 2); i += 256) {
            int s = i / (HDIM / 2), ii = i % (HDIM / 2);
            float c = g_cos[s * (HDIM / 2) + ii];
            float sn = g_sin[s * (HDIM / 2) + ii];
            float xr = s_a[s * HDIM + 2 * ii], xi = s_a[s * HDIM + 2 * ii + 1];
            s_a[s * HDIM + 2 * ii]     = xr * c - xi * sn;
            s_a[s * HDIM + 2 * ii + 1] = xr * sn + xi * c;
            xr = s_k[s * HDIM + 2 * ii]; xi = s_k[s * HDIM + 2 * ii + 1];
            s_k[s * HDIM + 2 * ii]     = xr * c - xi * sn;
            s_k[s * HDIM + 2 * ii + 1] = xr * sn + xi * c;
        }
        __syncthreads();
    }

    const float scale = 0.125f;
    for (int idx = tid; idx < S * S; idx += 256) {
        int i2 = idx / S, j = idx % S;
        if (rope_mask && j > i2) { s_sc[idx] = -INFINITY; continue; }
        const float4* qr = (const float4*)(s_a + i2 * HDIM);
        const float4* kr = (const float4*)(s_k + j * HDIM);
        float acc = 0.f;
#pragma unroll
        for (int d4 = 0; d4 < HDIM / 4; d4++) {
            float4 a = qr[d4], b = kr[d4];
            acc += a.x * b.x + a.y * b.y + a.z * b.z + a.w * b.w;
        }
        s_sc[idx] = acc * scale;
    }
    __syncthreads();

    int tpr = 256 / S;
    int row = tid / tpr, g = tid % tpr;
    float m = -INFINITY;
    for (int j = g; j < S; j += tpr) m = fmaxf(m, s_sc[row * S + j]);
    for (int off = tpr >> 1; off; off >>= 1) m = fmaxf(m, __shfl_xor_sync(0xffffffffu, m, off));
    float sum = 0.f;
    for (int j = g; j < S; j += tpr) {
        float e = __expf(s_sc[row * S + j] - m);
        s_sc[row * S + j] = e;
        sum += e;
    }
    for (int off = tpr >> 1; off; off >>= 1) sum += __shfl_xor_sync(0xffffffffu, sum, off);
    float inv = 1.0f / sum;
    for (int j = g; j < S; j += tpr) s_sc[row * S + j] *= inv;
    __syncthreads();

    for (int i = tid; i < S * HDIM; i += 256) {
        int s = i / HDIM, d = i % HDIM;
        s_a[i] = g_qkv[(rowbase + s) * 1536 + 1024 + h * HDIM + d];
    }
    __syncthreads();

    for (int idx = tid; idx < S * HDIM; idx += 256) {
        int i2 = idx / HDIM, d = idx % HDIM;
        float acc = 0.f;
        for (int j = 0; j < S; j++) acc += s_sc[i2 * S + j] * s_a[j * HDIM + d];
        size_t o = (rowbase + i2) * DIM + h * HDIM + d;
        __nv_bfloat16 hh = __float2bfloat16(acc);
        g_att16H[o] = hh;
        g_att16L[o] = __float2bfloat16(acc - __bfloat162float(hh));
    }
}

// ---------------- head GEMM ----------------
__global__ void __launch_bounds__(256) head_kernel(const float* __restrict__ Bw,
                                                   const float* __restrict__ bias) {
    int r = blockIdx.x;
    int n0 = blockIdx.y * 8;
    const float* arow = g_hn + (size_t)r * (PNUM * DIM);
    float acc[8] = {0.f, 0.f, 0.f, 0.f, 0.f, 0.f, 0.f, 0.f};
    for (int kidx = threadIdx.x; kidx < PNUM * DIM; kidx += 256) {
        float a = arow[kidx];
        const float* br = Bw + (size_t)kidx * PRED + n0;
#pragma unroll
        for (int j = 0; j < 8; j++) acc[j] += a * br[j];
    }
    __shared__ float sh[8][8];
    int lane = threadIdx.x & 31, wid = threadIdx.x >> 5;
#pragma unroll
    for (int j = 0; j < 8; j++) {
        float v = acc[j];
        for (int off = 16; off; off >>= 1) v += __shfl_xor_sync(0xffffffffu, v, off);
        if (lane == 0) sh[wid][j] = v;
    }
    __syncthreads();
    if (threadIdx.x < 8) {
        float s2 = 0.f;
#pragma unroll
        for (int w = 0; w < 8; w++) s2 += sh[w][threadIdx.x];
        g_z[(size_t)r * PRED + n0 + threadIdx.x] = s2 + bias[n0 + threadIdx.x];
    }
}

__global__ void finalize_kernel(float* __restrict__ out) {
    int i = blockIdx.x * blockDim.x + threadIdx.x;
    if (i >= BSZ * PRED * NVAR) return;
    int v = i % NVAR;
    int bt = i / NVAR;
    int t = bt % PRED;
    int b = bt / PRED;
    int bv = b * NVAR + v;
    out[i] = g_z[(size_t)bv * PRED + t] * g_std[bv] + g_mean[bv];
}

// ---------------- driver ----------------
extern "C" void kernel_launch(void* const* d_in, const int* in_sizes, int n_in,
                              void* d_out, int out_size) {
    const float* in[24];
    for (int i = 0; i < 24 && i < n_in; i++) in[i] = (const float*)d_in[i];

    const float *tokens = in[0], *pe_w = in[1], *pe_b = in[2];
    const float *norm_w, *head_w, *head_b;
    const float* W[2][9];

    if (in_sizes[3] == 512) {
        norm_w = in[3]; head_w = in[4]; head_b = in[5];
        for (int s = 0; s < 2; s++)
            for (int j = 0; j < 9; j++) W[s][j] = in[6 + s * 9 + j];
    } else {
        for (int s = 0; s < 2; s++)
            for (int j = 0; j < 9; j++) W[s][j] = in[3 + s * 9 + j];
        norm_w = in[21]; head_w = in[22]; head_b = in[23];
    }

    cudaFuncSetAttribute(tc_gemm, cudaFuncAttributeMaxDynamicSharedMemorySize, GEMM_SMEM);

    stats_kernel<<<BSZ * NVAR, 128>>>(tokens);                 // 0
    rope_init_kernel<<<PNUM, HDIM / 2>>>();                    // 1
    patch_embed_kernel<<<BSZ * PNUM, 256>>>(tokens, pe_w, pe_b); // 2

    for (int stage = 0; stage < 2; stage++) {
        int S = stage ? PNUM : NVAR;
        int nb = TOK / S;
        int stream_sel = stage ? BUF_HB : BUF_HA;
        for (int i = 0; i < NLAYER; i++) {
            size_t base = ((size_t)stage * NLAYER + i) * WT_LAYER;
            const float* wq = W[stage][0] + (size_t)i * DIM * DIM;
            const float* wk = W[stage][1] + (size_t)i * DIM * DIM;
            const float* wv = W[stage][2] + (size_t)i * DIM * DIM;
            const float* wo = W[stage][3] + (size_t)i * DIM * DIM;
            const float* w1 = W[stage][4] + (size_t)i * DIM * HIDDEN;
            const float* w2 = W[stage][5] + (size_t)i * HIDDEN * DIM;
            const float* w3 = W[stage][6] + (size_t)i * DIM * HIDDEN;
            const float* an = W[stage][7] + (size_t)i * DIM;
            const float* fn = W[stage][8] + (size_t)i * DIM;

            wprep_qkv_kernel<<<dim3(48, 16), dim3(32, 8)>>>(wq, wk, wv, base + OFF_QKV); // L0: 3
            rmsnorm16_kernel<<<TOK, 128>>>(stream_sel, 0, an);                           // L0: 4
            tc_gemm<<<dim3(6, 512), 256, GEMM_SMEM>>>(0, base + OFF_QKV, 0, BUF_QKV, -1, TOK, 1536, 512); // L0: 5
            attention_kernel<<<dim3(NHEAD, nb), 256>>>(S, stage);
            wprep_kernel<<<dim3(16, 16), dim3(32, 8)>>>(wo, base + OFF_O, 512, 512);
            tc_gemm<<<dim3(2, 512), 256, GEMM_SMEM>>>(1, base + OFF_O, 0, stream_sel, stream_sel, TOK, 512, 512);
            rmsnorm16_kernel<<<TOK, 128>>>(stream_sel, 0, fn);
            wprep13_kernel<<<dim3(96, 16), dim3(32, 8)>>>(w1, w3, base + OFF_W13);
            tc_gemm<<<dim3(12, 512), 256, GEMM_SMEM>>>(0, base + OFF_W13, 1, 0, -1, TOK, 3072, 512);
            wprep_kernel<<<dim3(16, 48), dim3(32, 8)>>>(w2, base + OFF_W2, 1536, 512);
            tc_gemm<<<dim3(2, 512), 256, GEMM_SMEM>>>(2, base + OFF_W2, 0, stream_sel, stream_sel, TOK, 512, 1536);
        }
        if (stage == 0) transition_kernel<<<TOK, 128>>>(norm_w);
    }

    rmsnorm_kernel<<<TOK, 128>>>(BUF_HB, BUF_HN, norm_w);
    head_kernel<<<dim3(BSZ * NVAR, PRED / 8), 256>>>(head_w, head_b);
    finalize_kernel<<<(BSZ * PRED * NVAR + 255) / 256, 256>>>((float*)d_out);
    (void)out_size; (void)n_in;
}